// round 8
// baseline (speedup 1.0000x reference)
#include <cuda_runtime.h>

#define BATCH 2
#define SEQ   2048
#define EMB   1024
#define NH    16
#define HD    64
#define MTOT  (BATCH * SEQ)   // 4096

// Scratch (device globals). Values stored tf32-rounded.
// g_K: [token][64] with head-dim columns permuted within 8-groups.
// g_Vt: [64][MTOT] transposed V, token index permuted within 8-groups.
__device__ float g_Q[(size_t)MTOT * EMB];
__device__ float g_K[(size_t)MTOT * HD];
__device__ float g_Vt[(size_t)HD * MTOT];

// logical j -> physical 2*(j&3)+(j>>2) within 8-groups; pairs (j,j+4)->(2j,2j+1)
__device__ __constant__ int c_pp[4][2] = {{0,2},{4,6},{1,3},{5,7}};  // tig -> (p0,p1) for (2tig,2tig+1)

__device__ __forceinline__ unsigned f2tf(float f) {
    unsigned u; asm("cvt.rna.tf32.f32 %0, %1;" : "=r"(u) : "f"(f)); return u;
}

__device__ __forceinline__ void cp16(void* dst_smem, const void* src) {
    unsigned d = (unsigned)__cvta_generic_to_shared(dst_smem);
    asm volatile("cp.async.cg.shared.global [%0], [%1], 16;\n" :: "r"(d), "l"(src));
}

// D += A@B, m16n8k8 tf32.
__device__ __forceinline__ void mma8(float* d, unsigned a0, unsigned a1,
                                     unsigned a2, unsigned a3,
                                     unsigned b0, unsigned b1) {
    asm volatile("mma.sync.aligned.m16n8k8.row.col.f32.tf32.tf32.f32 "
        "{%0,%1,%2,%3},{%4,%5,%6,%7},{%8,%9},{%0,%1,%2,%3};"
        : "+f"(d[0]), "+f"(d[1]), "+f"(d[2]), "+f"(d[3])
        : "r"(a0), "r"(a1), "r"(a2), "r"(a3), "r"(b0), "r"(b1));
}

// ---------------------------------------------------------------------------
// Fused QKV projection GEMM. BM=128,BN=64,BK=64.
// K epilogue: head-dim permuted. V epilogue: transposed + token-permuted.
// ---------------------------------------------------------------------------
__global__ __launch_bounds__(256) void qkv_gemm(
    const float* __restrict__ X, const float* __restrict__ Wq,
    const float* __restrict__ Wk, const float* __restrict__ Wv)
{
    const int nb = blockIdx.x;
    const int m0 = blockIdx.y * 128;

    const float* W; int ldw, wc0;
    if (nb < 16)      { W = Wq; ldw = EMB; wc0 = nb * 64; }
    else if (nb == 16){ W = Wk; ldw = HD;  wc0 = 0; }
    else              { W = Wv; ldw = HD;  wc0 = 0; }

    __shared__ unsigned As[128][68];
    __shared__ unsigned Bs[64][72];

    const int tid = threadIdx.x;
    const int wid = tid >> 5, lane = tid & 31;
    const int g = lane >> 2, tig = lane & 3;
    const int wm = wid >> 1, wn = wid & 1;

    float acc[2][4][4];
#pragma unroll
    for (int mt = 0; mt < 2; mt++)
#pragma unroll
        for (int nt = 0; nt < 4; nt++)
#pragma unroll
            for (int c = 0; c < 4; c++) acc[mt][nt][c] = 0.f;

    for (int k0 = 0; k0 < EMB; k0 += 64) {
#pragma unroll
        for (int l = 0; l < 8; l++) {
            int fid = tid + l * 256; int row = fid >> 4, c4 = fid & 15;
            float4 v = *(const float4*)&X[(size_t)(m0 + row) * EMB + k0 + c4 * 4];
            *(uint4*)&As[row][c4 * 4] = make_uint4(f2tf(v.x), f2tf(v.y), f2tf(v.z), f2tf(v.w));
        }
#pragma unroll
        for (int l = 0; l < 4; l++) {
            int fid = tid + l * 256; int kr = fid >> 4, c4 = fid & 15;
            float4 v = *(const float4*)&W[(size_t)(k0 + kr) * ldw + wc0 + c4 * 4];
            *(uint4*)&Bs[kr][c4 * 4] = make_uint4(f2tf(v.x), f2tf(v.y), f2tf(v.z), f2tf(v.w));
        }
        __syncthreads();

#pragma unroll
        for (int ks = 0; ks < 8; ks++) {
            int k = ks * 8;
            unsigned a[2][4], b[4][2];
#pragma unroll
            for (int mt = 0; mt < 2; mt++) {
                a[mt][0] = As[wm * 32 + mt * 16 +     g][k + tig];
                a[mt][1] = As[wm * 32 + mt * 16 + 8 + g][k + tig];
                a[mt][2] = As[wm * 32 + mt * 16 +     g][k + tig + 4];
                a[mt][3] = As[wm * 32 + mt * 16 + 8 + g][k + tig + 4];
            }
#pragma unroll
            for (int nt = 0; nt < 4; nt++) {
                b[nt][0] = Bs[k + tig    ][wn * 32 + nt * 8 + g];
                b[nt][1] = Bs[k + tig + 4][wn * 32 + nt * 8 + g];
            }
#pragma unroll
            for (int mt = 0; mt < 2; mt++)
#pragma unroll
                for (int nt = 0; nt < 4; nt++)
                    mma8(acc[mt][nt], a[mt][0], a[mt][1], a[mt][2], a[mt][3],
                         b[nt][0], b[nt][1]);
        }
        __syncthreads();
    }

    const int p0 = c_pp[tig][0], p1 = c_pp[tig][1];
#pragma unroll
    for (int mt = 0; mt < 2; mt++) {
        int r0 = m0 + wm * 32 + mt * 16 + g;     // global token / row
        int r1 = r0 + 8;
#pragma unroll
        for (int nt = 0; nt < 4; nt++) {
            float v00 = __uint_as_float(f2tf(acc[mt][nt][0]));
            float v01 = __uint_as_float(f2tf(acc[mt][nt][1]));
            float v10 = __uint_as_float(f2tf(acc[mt][nt][2]));
            float v11 = __uint_as_float(f2tf(acc[mt][nt][3]));
            if (nb < 16) {
                int c = nb * 64 + wn * 32 + nt * 8 + 2 * tig;
                *(float2*)&g_Q[(size_t)r0 * EMB + c] = make_float2(v00, v01);
                *(float2*)&g_Q[(size_t)r1 * EMB + c] = make_float2(v10, v11);
            } else if (nb == 16) {
                // K: permute head-dim within 8-group
                int gb = wn * 32 + nt * 8;
                g_K[(size_t)r0 * HD + gb + p0] = v00;
                g_K[(size_t)r0 * HD + gb + p1] = v01;
                g_K[(size_t)r1 * HD + gb + p0] = v10;
                g_K[(size_t)r1 * HD + gb + p1] = v11;
            } else {
                // V: transpose to g_Vt[d][token], token permuted within 8-group
                int d = wn * 32 + nt * 8 + 2 * tig;
                int tp0 = (r0 & ~7) | (2 * (g & 3) + (g >> 2));  // r0 low3 == g
                int tp1 = tp0 + 8;
                g_Vt[(size_t)d       * MTOT + tp0] = v00;
                g_Vt[(size_t)(d + 1) * MTOT + tp0] = v01;
                g_Vt[(size_t)d       * MTOT + tp1] = v10;
                g_Vt[(size_t)(d + 1) * MTOT + tp1] = v11;
            }
        }
    }
}

// ---------------------------------------------------------------------------
// Flash attention, m16n8k8 tf32, cp.async double-buffered K/V^T.
// 8 warps = 2 heads per CTA (MQA). Pair-permuted layouts -> LDS.64 fragments.
// Private P buffer per head group -> only 2 __syncthreads per tile.
// smem: K 2x + Vt 2x + P 2x, each 64x68 words = 102 KB -> 2 CTAs/SM.
// ---------------------------------------------------------------------------
#define TW 4352   // 64*68 words
#define ATTN_SMEM (6 * TW * 4)

__global__ __launch_bounds__(256) void attn_mma(float* __restrict__ out)
{
    extern __shared__ unsigned smem_dyn[];
    unsigned* SK  = smem_dyn;            // [2][64][68] K rows=t, cols=d-perm
    unsigned* SVT = smem_dyn + 2 * TW;   // [2][64][68] V^T rows=d, cols=t-perm
    unsigned* SPB = smem_dyn + 4 * TW;   // [2][64][68] P per head group

    const int qt = gridDim.x - 1 - blockIdx.x;  // long CTAs first
    const int hp = blockIdx.y;
    const int b  = blockIdx.z;
    const int qbase = qt * 64;

    const int tid = threadIdx.x;
    const int wid = tid >> 5, lane = tid & 31;
    const int g = lane >> 2, tig = lane & 3;
    const int hgrp = wid >> 2;
    const int wg   = wid & 3;
    const int h    = hp * 2 + hgrp;

    const int r0 = qbase + wg * 16 + g;
    const int r1 = r0 + 8;
    const int p0 = c_pp[tig][0], p1 = c_pp[tig][1];

    unsigned* P = SPB + hgrp * TW;

    auto issue = [&](int kt) {
        const int bf = kt & 1, kbase = kt * 64;
        const float4* Kp = (const float4*)(g_K + (size_t)(b * SEQ + kbase) * HD);
#pragma unroll
        for (int l = 0; l < 4; l++) {
            int fid = tid + l * 256; int row = fid >> 4, c4 = fid & 15;
            cp16(&SK[bf * TW + row * 68 + c4 * 4], &Kp[row * 16 + c4]);
            cp16(&SVT[bf * TW + row * 68 + c4 * 4],
                 g_Vt + (size_t)row * MTOT + b * SEQ + kbase + c4 * 4);
        }
        asm volatile("cp.async.commit_group;\n");
    };

    issue(0);

    // Q A-fragments in registers (g_Q unpermuted; tf32-prerounded)
    unsigned q[8][4];
    {
        const unsigned* Q0 = (const unsigned*)(g_Q + (size_t)(b * SEQ + r0) * EMB + h * HD);
        const unsigned* Q1 = (const unsigned*)(g_Q + (size_t)(b * SEQ + r1) * EMB + h * HD);
#pragma unroll
        for (int ks = 0; ks < 8; ks++) {
            int k = ks * 8;
            q[ks][0] = Q0[k + tig];
            q[ks][1] = Q1[k + tig];
            q[ks][2] = Q0[k + tig + 4];
            q[ks][3] = Q1[k + tig + 4];
        }
    }

    float l0 = 0.f, l1 = 0.f;
    float o[8][4];
#pragma unroll
    for (int nt = 0; nt < 8; nt++)
#pragma unroll
        for (int c = 0; c < 4; c++) o[nt][c] = 0.f;

    const float cs = 0.125f * 1.44269504f;  // scale * log2(e)

    for (int kt = 0; kt <= qt; kt++) {
        const int bf = kt & 1;
        const int kbase = kt * 64;

        __syncthreads();                // all reads of buf[bf^1] done
        if (kt < qt) {
            issue(kt + 1);
            asm volatile("cp.async.wait_group 1;\n");
        } else {
            asm volatile("cp.async.wait_group 0;\n");
        }
        __syncthreads();                // buf[bf] visible to all warps

        // S = Q K^T  (K cols d-permuted -> b-pairs are LDS.64)
        float s[8][4];
#pragma unroll
        for (int nt = 0; nt < 8; nt++)
#pragma unroll
            for (int c = 0; c < 4; c++) s[nt][c] = 0.f;

#pragma unroll
        for (int ks = 0; ks < 8; ks++) {
            int k = ks * 8;
#pragma unroll
            for (int nt = 0; nt < 8; nt++) {
                uint2 bb = *(const uint2*)&SK[bf * TW + (nt * 8 + g) * 68 + k + 2 * tig];
                mma8(s[nt], q[ks][0], q[ks][1], q[ks][2], q[ks][3], bb.x, bb.y);
            }
        }

        // p = 2^(s*cs); masked -> 0; accumulate l per-thread
        if (kt == qt) {
#pragma unroll
            for (int nt = 0; nt < 8; nt++) {
                int c = kbase + nt * 8 + 2 * tig;
                s[nt][0] = (c     <= r0) ? exp2f(s[nt][0] * cs) : 0.f;
                s[nt][1] = (c + 1 <= r0) ? exp2f(s[nt][1] * cs) : 0.f;
                s[nt][2] = (c     <= r1) ? exp2f(s[nt][2] * cs) : 0.f;
                s[nt][3] = (c + 1 <= r1) ? exp2f(s[nt][3] * cs) : 0.f;
                l0 += s[nt][0] + s[nt][1];
                l1 += s[nt][2] + s[nt][3];
            }
        } else {
#pragma unroll
            for (int nt = 0; nt < 8; nt++) {
                s[nt][0] = exp2f(s[nt][0] * cs);
                s[nt][1] = exp2f(s[nt][1] * cs);
                s[nt][2] = exp2f(s[nt][2] * cs);
                s[nt][3] = exp2f(s[nt][3] * cs);
                l0 += s[nt][0] + s[nt][1];
                l1 += s[nt][2] + s[nt][3];
            }
        }

        // P -> private buffer, t-permuted columns (match V^T). No CTA sync:
        // each warp reads back only rows it wrote.
#pragma unroll
        for (int nt = 0; nt < 8; nt++) {
            int rr = wg * 16 + g, gb = nt * 8;
            P[(rr    ) * 68 + gb + p0] = __float_as_uint(s[nt][0]);
            P[(rr    ) * 68 + gb + p1] = __float_as_uint(s[nt][1]);
            P[(rr + 8) * 68 + gb + p0] = __float_as_uint(s[nt][2]);
            P[(rr + 8) * 68 + gb + p1] = __float_as_uint(s[nt][3]);
        }
        __syncwarp();

        // O += P V   (a-pairs and b-pairs both LDS.64)
#pragma unroll
        for (int ks = 0; ks < 8; ks++) {
            int k = ks * 8;
            uint2 aa0 = *(const uint2*)&P[(wg * 16 +     g) * 68 + k + 2 * tig];
            uint2 aa1 = *(const uint2*)&P[(wg * 16 + 8 + g) * 68 + k + 2 * tig];
#pragma unroll
            for (int nt = 0; nt < 8; nt++) {
                uint2 bb = *(const uint2*)&SVT[bf * TW + (nt * 8 + g) * 68 + k + 2 * tig];
                mma8(o[nt], aa0.x, aa1.x, aa0.y, aa1.y, bb.x, bb.y);
            }
        }
    }

    // epilogue
    l0 += __shfl_xor_sync(0xffffffffu, l0, 1);
    l0 += __shfl_xor_sync(0xffffffffu, l0, 2);
    l1 += __shfl_xor_sync(0xffffffffu, l1, 1);
    l1 += __shfl_xor_sync(0xffffffffu, l1, 2);
    float i0 = 1.f / l0, i1 = 1.f / l1;
    float* Op = out + (size_t)b * SEQ * EMB + h * HD;
#pragma unroll
    for (int nt = 0; nt < 8; nt++) {
        int c = nt * 8 + 2 * tig;
        *(float2*)&Op[(size_t)r0 * EMB + c] = make_float2(o[nt][0] * i0, o[nt][1] * i0);
        *(float2*)&Op[(size_t)r1 * EMB + c] = make_float2(o[nt][2] * i1, o[nt][3] * i1);
    }
}

// ---------------------------------------------------------------------------
extern "C" void kernel_launch(void* const* d_in, const int* in_sizes, int n_in,
                              void* d_out, int out_size)
{
    (void)in_sizes; (void)n_in; (void)out_size;
    const float* X  = (const float*)d_in[0];
    const float* Wq = (const float*)d_in[1];
    const float* Wk = (const float*)d_in[2];
    const float* Wv = (const float*)d_in[3];
    float* out = (float*)d_out;

    static bool attr_set = false;
    if (!attr_set) {
        cudaFuncSetAttribute(attn_mma, cudaFuncAttributeMaxDynamicSharedMemorySize, ATTN_SMEM);
        attr_set = true;
    }

    qkv_gemm<<<dim3(18, MTOT / 128), 256>>>(X, Wq, Wk, Wv);
    attn_mma<<<dim3(SEQ / 64, NH / 2, BATCH), 256, ATTN_SMEM>>>(out);
}

// round 9
// speedup vs baseline: 1.9810x; 1.9810x over previous
#include <cuda_runtime.h>
#include <cuda_fp16.h>

#define BATCH 2
#define SEQ   2048
#define EMB   1024
#define NH    16
#define HD    64
#define MTOT  (BATCH * SEQ)   // 4096

// Scratch (device globals). Attention operands stored fp16.
__device__ __half g_Q[(size_t)MTOT * EMB];    // [token][emb]
__device__ __half g_K[(size_t)MTOT * HD];     // [token][d]
__device__ __half g_Vt[(size_t)HD * MTOT];    // [d][token]  (transposed V)

__device__ __forceinline__ unsigned f2tf(float f) {
    unsigned u; asm("cvt.rna.tf32.f32 %0, %1;" : "=r"(u) : "f"(f)); return u;
}

__device__ __forceinline__ void cp16(void* dst_smem, const void* src) {
    unsigned d = (unsigned)__cvta_generic_to_shared(dst_smem);
    asm volatile("cp.async.cg.shared.global [%0], [%1], 16;\n" :: "r"(d), "l"(src));
}

// tf32 m16n8k8 (projection GEMM)
__device__ __forceinline__ void mma8(float* d, unsigned a0, unsigned a1,
                                     unsigned a2, unsigned a3,
                                     unsigned b0, unsigned b1) {
    asm volatile("mma.sync.aligned.m16n8k8.row.col.f32.tf32.tf32.f32 "
        "{%0,%1,%2,%3},{%4,%5,%6,%7},{%8,%9},{%0,%1,%2,%3};"
        : "+f"(d[0]), "+f"(d[1]), "+f"(d[2]), "+f"(d[3])
        : "r"(a0), "r"(a1), "r"(a2), "r"(a3), "r"(b0), "r"(b1));
}

// fp16 m16n8k16, fp32 accumulate (attention).
// A(row): a0=(g,2t..2t+1) a1=(g+8,·) a2=(g,2t+8..9) a3=(g+8,·)
// B(col): b0=(2t..2t+1,g) b1=(2t+8..9,g)
// C: c0=(g,2t) c1=(g,2t+1) c2=(g+8,2t) c3=(g+8,2t+1)
__device__ __forceinline__ void mma16(float* d, unsigned a0, unsigned a1,
                                      unsigned a2, unsigned a3,
                                      unsigned b0, unsigned b1) {
    asm volatile("mma.sync.aligned.m16n8k16.row.col.f32.f16.f16.f32 "
        "{%0,%1,%2,%3},{%4,%5,%6,%7},{%8,%9},{%0,%1,%2,%3};"
        : "+f"(d[0]), "+f"(d[1]), "+f"(d[2]), "+f"(d[3])
        : "r"(a0), "r"(a1), "r"(a2), "r"(a3), "r"(b0), "r"(b1));
}

// ---------------------------------------------------------------------------
// Fused QKV projection GEMM (tf32 core, fp16 epilogue). BM=128,BN=64,BK=64.
// blockIdx.x: 0..15 -> Q blocks; 16 -> K; 17 -> V (stored transposed).
// ---------------------------------------------------------------------------
__global__ __launch_bounds__(256) void qkv_gemm(
    const float* __restrict__ X, const float* __restrict__ Wq,
    const float* __restrict__ Wk, const float* __restrict__ Wv)
{
    const int nb = blockIdx.x;
    const int m0 = blockIdx.y * 128;

    const float* W; int ldw, wc0;
    if (nb < 16)      { W = Wq; ldw = EMB; wc0 = nb * 64; }
    else if (nb == 16){ W = Wk; ldw = HD;  wc0 = 0; }
    else              { W = Wv; ldw = HD;  wc0 = 0; }

    __shared__ unsigned As[128][68];
    __shared__ unsigned Bs[64][72];

    const int tid = threadIdx.x;
    const int wid = tid >> 5, lane = tid & 31;
    const int g = lane >> 2, tig = lane & 3;
    const int wm = wid >> 1, wn = wid & 1;

    float acc[2][4][4];
#pragma unroll
    for (int mt = 0; mt < 2; mt++)
#pragma unroll
        for (int nt = 0; nt < 4; nt++)
#pragma unroll
            for (int c = 0; c < 4; c++) acc[mt][nt][c] = 0.f;

    for (int k0 = 0; k0 < EMB; k0 += 64) {
#pragma unroll
        for (int l = 0; l < 8; l++) {
            int fid = tid + l * 256; int row = fid >> 4, c4 = fid & 15;
            float4 v = *(const float4*)&X[(size_t)(m0 + row) * EMB + k0 + c4 * 4];
            *(uint4*)&As[row][c4 * 4] = make_uint4(f2tf(v.x), f2tf(v.y), f2tf(v.z), f2tf(v.w));
        }
#pragma unroll
        for (int l = 0; l < 4; l++) {
            int fid = tid + l * 256; int kr = fid >> 4, c4 = fid & 15;
            float4 v = *(const float4*)&W[(size_t)(k0 + kr) * ldw + wc0 + c4 * 4];
            *(uint4*)&Bs[kr][c4 * 4] = make_uint4(f2tf(v.x), f2tf(v.y), f2tf(v.z), f2tf(v.w));
        }
        __syncthreads();

#pragma unroll
        for (int ks = 0; ks < 8; ks++) {
            int k = ks * 8;
            unsigned a[2][4], b[4][2];
#pragma unroll
            for (int mt = 0; mt < 2; mt++) {
                a[mt][0] = As[wm * 32 + mt * 16 +     g][k + tig];
                a[mt][1] = As[wm * 32 + mt * 16 + 8 + g][k + tig];
                a[mt][2] = As[wm * 32 + mt * 16 +     g][k + tig + 4];
                a[mt][3] = As[wm * 32 + mt * 16 + 8 + g][k + tig + 4];
            }
#pragma unroll
            for (int nt = 0; nt < 4; nt++) {
                b[nt][0] = Bs[k + tig    ][wn * 32 + nt * 8 + g];
                b[nt][1] = Bs[k + tig + 4][wn * 32 + nt * 8 + g];
            }
#pragma unroll
            for (int mt = 0; mt < 2; mt++)
#pragma unroll
                for (int nt = 0; nt < 4; nt++)
                    mma8(acc[mt][nt], a[mt][0], a[mt][1], a[mt][2], a[mt][3],
                         b[nt][0], b[nt][1]);
        }
        __syncthreads();
    }

#pragma unroll
    for (int mt = 0; mt < 2; mt++) {
        int r0 = m0 + wm * 32 + mt * 16 + g;
        int r1 = r0 + 8;
#pragma unroll
        for (int nt = 0; nt < 4; nt++) {
            int c = wn * 32 + nt * 8 + 2 * tig;
            __half2 h0 = __floats2half2_rn(acc[mt][nt][0], acc[mt][nt][1]);
            __half2 h1 = __floats2half2_rn(acc[mt][nt][2], acc[mt][nt][3]);
            if (nb < 16) {
                int cc = nb * 64 + c;
                *(__half2*)&g_Q[(size_t)r0 * EMB + cc] = h0;
                *(__half2*)&g_Q[(size_t)r1 * EMB + cc] = h1;
            } else if (nb == 16) {
                *(__half2*)&g_K[(size_t)r0 * HD + c] = h0;
                *(__half2*)&g_K[(size_t)r1 * HD + c] = h1;
            } else {
                // V transposed: g_Vt[d][token]
                g_Vt[(size_t)c       * MTOT + r0] = __low2half(h0);
                g_Vt[(size_t)(c + 1) * MTOT + r0] = __high2half(h0);
                g_Vt[(size_t)c       * MTOT + r1] = __low2half(h1);
                g_Vt[(size_t)(c + 1) * MTOT + r1] = __high2half(h1);
            }
        }
    }
}

// ---------------------------------------------------------------------------
// Flash attention, fp16 m16n8k16, cp.async double-buffered K/V^T.
// CTA = 64 q-rows x head x batch, 4 warps, Q in registers.
// smem rows padded to 36 words (72 halves): (4g+tig) distinct mod 32 ->
// all fragment LDS and P STS conflict-free. Private P buffer -> 2 syncs/tile.
// smem: K 2x + Vt 2x + P = 5 * 64*36 words = 46 KB -> 4 CTAs/SM.
// ---------------------------------------------------------------------------
#define TW (64 * 36)          // words per tile buffer
#define ATTN_SMEM (5 * TW * 4)

__global__ __launch_bounds__(128) void attn_mma(float* __restrict__ out)
{
    extern __shared__ unsigned smem_dyn[];
    unsigned* SK  = smem_dyn;            // [2][64][36w] K rows=t, 64 halves + pad
    unsigned* SVT = smem_dyn + 2 * TW;   // [2][64][36w] V^T rows=d
    unsigned* SP  = smem_dyn + 4 * TW;   // [64][36w]    P rows=r (fp16)

    const int qt = gridDim.x - 1 - blockIdx.x;  // long CTAs first
    const int h  = blockIdx.y;
    const int b  = blockIdx.z;
    const int qbase = qt * 64;

    const int tid = threadIdx.x;
    const int wid = tid >> 5, lane = tid & 31;
    const int g = lane >> 2, tig = lane & 3;

    const int r0 = qbase + wid * 16 + g;
    const int r1 = r0 + 8;

    auto issue = [&](int kt) {
        const int bf = kt & 1, kbase = kt * 64;
        const __half* Kp  = g_K + (size_t)(b * SEQ + kbase) * HD;
        const __half* Vtp = g_Vt;  // row d stride MTOT
#pragma unroll
        for (int l = 0; l < 4; l++) {
            int fid = tid + l * 128; int row = fid >> 3, c4 = fid & 7;
            cp16(&SK[bf * TW + row * 36 + c4 * 4], Kp + row * HD + c4 * 8);
            cp16(&SVT[bf * TW + row * 36 + c4 * 4],
                 Vtp + (size_t)row * MTOT + b * SEQ + kbase + c4 * 8);
        }
        asm volatile("cp.async.commit_group;\n");
    };

    issue(0);

    // Q A-fragments in registers (fp16; 4 k-chunks of 16)
    unsigned q[4][4];
    {
        const __half* Q0 = g_Q + (size_t)(b * SEQ + r0) * EMB + h * HD;
        const __half* Q1 = g_Q + (size_t)(b * SEQ + r1) * EMB + h * HD;
#pragma unroll
        for (int kc = 0; kc < 4; kc++) {
            q[kc][0] = *(const unsigned*)(Q0 + kc * 16 + 2 * tig);
            q[kc][1] = *(const unsigned*)(Q1 + kc * 16 + 2 * tig);
            q[kc][2] = *(const unsigned*)(Q0 + kc * 16 + 2 * tig + 8);
            q[kc][3] = *(const unsigned*)(Q1 + kc * 16 + 2 * tig + 8);
        }
    }

    float l0 = 0.f, l1 = 0.f;
    float o[8][4];
#pragma unroll
    for (int nt = 0; nt < 8; nt++)
#pragma unroll
        for (int c = 0; c < 4; c++) o[nt][c] = 0.f;

    const float cs = 0.125f * 1.44269504f;  // scale * log2(e)

    for (int kt = 0; kt <= qt; kt++) {
        const int bf = kt & 1;
        const int kbase = kt * 64;

        __syncthreads();                // all reads of buf[bf^1] done
        if (kt < qt) {
            issue(kt + 1);
            asm volatile("cp.async.wait_group 1;\n");
        } else {
            asm volatile("cp.async.wait_group 0;\n");
        }
        __syncthreads();                // buf[bf] visible

        // S = Q K^T
        float s[8][4];
#pragma unroll
        for (int nt = 0; nt < 8; nt++)
#pragma unroll
            for (int c = 0; c < 4; c++) s[nt][c] = 0.f;

#pragma unroll
        for (int kc = 0; kc < 4; kc++) {
#pragma unroll
            for (int nt = 0; nt < 8; nt++) {
                unsigned b0 = SK[bf * TW + (nt * 8 + g) * 36 + kc * 8 + tig];
                unsigned b1 = SK[bf * TW + (nt * 8 + g) * 36 + kc * 8 + tig + 4];
                mma16(s[nt], q[kc][0], q[kc][1], q[kc][2], q[kc][3], b0, b1);
            }
        }

        // p = 2^(s*cs); masked -> 0; accumulate l per-thread
        if (kt == qt) {
#pragma unroll
            for (int nt = 0; nt < 8; nt++) {
                int c = kbase + nt * 8 + 2 * tig;
                s[nt][0] = (c     <= r0) ? exp2f(s[nt][0] * cs) : 0.f;
                s[nt][1] = (c + 1 <= r0) ? exp2f(s[nt][1] * cs) : 0.f;
                s[nt][2] = (c     <= r1) ? exp2f(s[nt][2] * cs) : 0.f;
                s[nt][3] = (c + 1 <= r1) ? exp2f(s[nt][3] * cs) : 0.f;
                l0 += s[nt][0] + s[nt][1];
                l1 += s[nt][2] + s[nt][3];
            }
        } else {
#pragma unroll
            for (int nt = 0; nt < 8; nt++) {
                s[nt][0] = exp2f(s[nt][0] * cs);
                s[nt][1] = exp2f(s[nt][1] * cs);
                s[nt][2] = exp2f(s[nt][2] * cs);
                s[nt][3] = exp2f(s[nt][3] * cs);
                l0 += s[nt][0] + s[nt][1];
                l1 += s[nt][2] + s[nt][3];
            }
        }

        // P (fp16) -> private buffer; each warp touches only its own 16 rows
#pragma unroll
        for (int nt = 0; nt < 8; nt++) {
            int rr = wid * 16 + g, wrd = nt * 4 + tig;
            *(__half2*)&SP[rr * 36 + wrd]       = __floats2half2_rn(s[nt][0], s[nt][1]);
            *(__half2*)&SP[(rr + 8) * 36 + wrd] = __floats2half2_rn(s[nt][2], s[nt][3]);
        }
        __syncwarp();

        // O += P V
#pragma unroll
        for (int kc = 0; kc < 4; kc++) {
            unsigned a0 = SP[(wid * 16 +     g) * 36 + kc * 8 + tig];
            unsigned a1 = SP[(wid * 16 + 8 + g) * 36 + kc * 8 + tig];
            unsigned a2 = SP[(wid * 16 +     g) * 36 + kc * 8 + tig + 4];
            unsigned a3 = SP[(wid * 16 + 8 + g) * 36 + kc * 8 + tig + 4];
#pragma unroll
            for (int nt = 0; nt < 8; nt++) {
                unsigned b0 = SVT[bf * TW + (nt * 8 + g) * 36 + kc * 8 + tig];
                unsigned b1 = SVT[bf * TW + (nt * 8 + g) * 36 + kc * 8 + tig + 4];
                mma16(o[nt], a0, a1, a2, a3, b0, b1);
            }
        }
    }

    // epilogue
    l0 += __shfl_xor_sync(0xffffffffu, l0, 1);
    l0 += __shfl_xor_sync(0xffffffffu, l0, 2);
    l1 += __shfl_xor_sync(0xffffffffu, l1, 1);
    l1 += __shfl_xor_sync(0xffffffffu, l1, 2);
    float i0 = 1.f / l0, i1 = 1.f / l1;
    float* Op = out + (size_t)b * SEQ * EMB + h * HD;
#pragma unroll
    for (int nt = 0; nt < 8; nt++) {
        int c = nt * 8 + 2 * tig;
        *(float2*)&Op[(size_t)r0 * EMB + c] = make_float2(o[nt][0] * i0, o[nt][1] * i0);
        *(float2*)&Op[(size_t)r1 * EMB + c] = make_float2(o[nt][2] * i1, o[nt][3] * i1);
    }
}

// ---------------------------------------------------------------------------
extern "C" void kernel_launch(void* const* d_in, const int* in_sizes, int n_in,
                              void* d_out, int out_size)
{
    (void)in_sizes; (void)n_in; (void)out_size;
    const float* X  = (const float*)d_in[0];
    const float* Wq = (const float*)d_in[1];
    const float* Wk = (const float*)d_in[2];
    const float* Wv = (const float*)d_in[3];
    float* out = (float*)d_out;

    static bool attr_set = false;
    if (!attr_set) {
        cudaFuncSetAttribute(attn_mma, cudaFuncAttributeMaxDynamicSharedMemorySize, ATTN_SMEM);
        attr_set = true;
    }

    qkv_gemm<<<dim3(18, MTOT / 128), 256>>>(X, Wq, Wk, Wv);
    attn_mma<<<dim3(SEQ / 64, NH, BATCH), 128, ATTN_SMEM>>>(out);
}

// round 10
// speedup vs baseline: 2.1118x; 1.0660x over previous
#include <cuda_runtime.h>
#include <cuda_fp16.h>

#define BATCH 2
#define SEQ   2048
#define EMB   1024
#define NH    16
#define HD    64
#define MTOT  (BATCH * SEQ)   // 4096

// Scratch (device globals). Attention operands stored fp16.
__device__ __half g_Q[(size_t)MTOT * EMB];    // [token][emb]
__device__ __half g_K[(size_t)MTOT * HD];     // [token][d]
__device__ __half g_Vt[(size_t)HD * MTOT];    // [d][token]

__device__ __forceinline__ void cp16(void* dst_smem, const void* src) {
    unsigned d = (unsigned)__cvta_generic_to_shared(dst_smem);
    asm volatile("cp.async.cg.shared.global [%0], [%1], 16;\n" :: "r"(d), "l"(src));
}

// fp16 m16n8k16, fp32 accumulate.
__device__ __forceinline__ void mma16(float* d, unsigned a0, unsigned a1,
                                      unsigned a2, unsigned a3,
                                      unsigned b0, unsigned b1) {
    asm volatile("mma.sync.aligned.m16n8k16.row.col.f32.f16.f16.f32 "
        "{%0,%1,%2,%3},{%4,%5,%6,%7},{%8,%9},{%0,%1,%2,%3};"
        : "+f"(d[0]), "+f"(d[1]), "+f"(d[2]), "+f"(d[3])
        : "r"(a0), "r"(a1), "r"(a2), "r"(a3), "r"(b0), "r"(b1));
}

__device__ __forceinline__ void ldsm4(unsigned& r0, unsigned& r1, unsigned& r2,
                                      unsigned& r3, unsigned addr) {
    asm volatile("ldmatrix.sync.aligned.m8n8.x4.shared.b16 {%0,%1,%2,%3}, [%4];"
        : "=r"(r0), "=r"(r1), "=r"(r2), "=r"(r3) : "r"(addr));
}
__device__ __forceinline__ void ldsm4t(unsigned& r0, unsigned& r1, unsigned& r2,
                                       unsigned& r3, unsigned addr) {
    asm volatile("ldmatrix.sync.aligned.m8n8.x4.trans.shared.b16 {%0,%1,%2,%3}, [%4];"
        : "=r"(r0), "=r"(r1), "=r"(r2), "=r"(r3) : "r"(addr));
}

// Row pitch everywhere: 72 halves = 36 words = 144 bytes (bank-quad friendly).
#define RB 144

// ---------------------------------------------------------------------------
// Fused QKV projection GEMM, fp16 m16n8k16 + LDSM. BM=128,BN=64,BK=64.
// blockIdx.x: 0..15 -> Q blocks; 16 -> K; 17 -> V (stored transposed).
// ---------------------------------------------------------------------------
__global__ __launch_bounds__(256) void qkv_gemm(
    const float* __restrict__ X, const float* __restrict__ Wq,
    const float* __restrict__ Wk, const float* __restrict__ Wv)
{
    const int nb = blockIdx.x;
    const int m0 = blockIdx.y * 128;

    const float* W; int ldw, wc0;
    if (nb < 16)      { W = Wq; ldw = EMB; wc0 = nb * 64; }
    else if (nb == 16){ W = Wk; ldw = HD;  wc0 = 0; }
    else              { W = Wv; ldw = HD;  wc0 = 0; }

    __shared__ __align__(16) __half As[128 * 72];  // [m][k halves], pitch 72
    __shared__ __align__(16) __half Bs[64 * 72];   // [k][n halves], pitch 72

    const int tid = threadIdx.x;
    const int wid = tid >> 5, lane = tid & 31;
    const int g = lane >> 2, tig = lane & 3;
    const int wm = wid >> 1, wn = wid & 1;

    const unsigned as_b = (unsigned)__cvta_generic_to_shared(As);
    const unsigned bs_b = (unsigned)__cvta_generic_to_shared(Bs);

    // a-frag lanes: rows lane&15, k-ext for lanes>=16
    const int rowA16 = lane & 15, khA = (lane >> 4) * 8;
    // trans b-frag lanes: k-rows +8 for lanes 8-15/24-31, col-ext for lanes>=16
    const int rowT = (lane & 7) + (((lane >> 3) & 1) * 8);
    const int colT = (lane >> 4) * 8;

    const unsigned a_base = as_b + (unsigned)((wm * 32 + rowA16) * RB + khA * 2);
    const unsigned b_base = bs_b + (unsigned)(rowT * RB + (wn * 32 + colT) * 2);

    float acc[2][4][4];
#pragma unroll
    for (int mt = 0; mt < 2; mt++)
#pragma unroll
        for (int nt = 0; nt < 4; nt++)
#pragma unroll
            for (int c = 0; c < 4; c++) acc[mt][nt][c] = 0.f;

    for (int k0 = 0; k0 < EMB; k0 += 64) {
        // A tile 128x64 fp32 -> fp16: 2048 float4, 8 per thread
#pragma unroll
        for (int l = 0; l < 8; l++) {
            int fid = tid + l * 256; int row = fid >> 4, c4 = fid & 15;
            float4 v = *(const float4*)&X[(size_t)(m0 + row) * EMB + k0 + c4 * 4];
            __half2 h01 = __floats2half2_rn(v.x, v.y);
            __half2 h23 = __floats2half2_rn(v.z, v.w);
            *(uint2*)&As[row * 72 + c4 * 4] =
                make_uint2(*(unsigned*)&h01, *(unsigned*)&h23);
        }
        // B tile 64x64: 1024 float4, 4 per thread
#pragma unroll
        for (int l = 0; l < 4; l++) {
            int fid = tid + l * 256; int row = fid >> 4, c4 = fid & 15;
            float4 v = *(const float4*)&W[(size_t)(k0 + row) * ldw + wc0 + c4 * 4];
            __half2 h01 = __floats2half2_rn(v.x, v.y);
            __half2 h23 = __floats2half2_rn(v.z, v.w);
            *(uint2*)&Bs[row * 72 + c4 * 4] =
                make_uint2(*(unsigned*)&h01, *(unsigned*)&h23);
        }
        __syncthreads();

#pragma unroll
        for (int kc = 0; kc < 4; kc++) {
            unsigned a[2][4], bb[4][2];
#pragma unroll
            for (int mt = 0; mt < 2; mt++)
                ldsm4(a[mt][0], a[mt][1], a[mt][2], a[mt][3],
                      a_base + mt * 16 * RB + kc * 32);
#pragma unroll
            for (int np = 0; np < 2; np++)
                ldsm4t(bb[np * 2][0], bb[np * 2][1], bb[np * 2 + 1][0], bb[np * 2 + 1][1],
                       b_base + kc * 16 * RB + np * 32);
#pragma unroll
            for (int mt = 0; mt < 2; mt++)
#pragma unroll
                for (int nt = 0; nt < 4; nt++)
                    mma16(acc[mt][nt], a[mt][0], a[mt][1], a[mt][2], a[mt][3],
                          bb[nt][0], bb[nt][1]);
        }
        __syncthreads();
    }

#pragma unroll
    for (int mt = 0; mt < 2; mt++) {
        int r0 = m0 + wm * 32 + mt * 16 + g;
        int r1 = r0 + 8;
#pragma unroll
        for (int nt = 0; nt < 4; nt++) {
            int c = wn * 32 + nt * 8 + 2 * tig;
            __half2 h0 = __floats2half2_rn(acc[mt][nt][0], acc[mt][nt][1]);
            __half2 h1 = __floats2half2_rn(acc[mt][nt][2], acc[mt][nt][3]);
            if (nb < 16) {
                int cc = nb * 64 + c;
                *(__half2*)&g_Q[(size_t)r0 * EMB + cc] = h0;
                *(__half2*)&g_Q[(size_t)r1 * EMB + cc] = h1;
            } else if (nb == 16) {
                *(__half2*)&g_K[(size_t)r0 * HD + c] = h0;
                *(__half2*)&g_K[(size_t)r1 * HD + c] = h1;
            } else {
                g_Vt[(size_t)c       * MTOT + r0] = __low2half(h0);
                g_Vt[(size_t)(c + 1) * MTOT + r0] = __high2half(h0);
                g_Vt[(size_t)c       * MTOT + r1] = __low2half(h1);
                g_Vt[(size_t)(c + 1) * MTOT + r1] = __high2half(h1);
            }
        }
    }
}

// ---------------------------------------------------------------------------
// Flash attention, fp16 m16n8k16, LDSM fragments, cp.async double buffering.
// CTA = 64 q-rows x head x batch, 4 warps, Q in registers.
// smem: K 2x + Vt 2x + P = 5 * 64*144B = 46 KB -> 4 CTAs/SM.
// ---------------------------------------------------------------------------
#define TW (64 * 36)          // words per tile buffer
#define TWB (64 * RB)         // bytes per tile buffer
#define ATTN_SMEM (5 * TW * 4)

__global__ __launch_bounds__(128) void attn_mma(float* __restrict__ out)
{
    extern __shared__ __align__(16) unsigned smem_dyn[];
    unsigned* SK  = smem_dyn;            // [2][64 rows t][36w] K
    unsigned* SVT = smem_dyn + 2 * TW;   // [2][64 rows d][36w] V^T
    unsigned* SP  = smem_dyn + 4 * TW;   // [64 rows r][36w]    P (fp16)

    const int qt = gridDim.x - 1 - blockIdx.x;  // long CTAs first
    const int h  = blockIdx.y;
    const int b  = blockIdx.z;
    const int qbase = qt * 64;

    const int tid = threadIdx.x;
    const int wid = tid >> 5, lane = tid & 31;
    const int g = lane >> 2, tig = lane & 3;

    const int r0 = qbase + wid * 16 + g;
    const int r1 = r0 + 8;

    const unsigned sk_b  = (unsigned)__cvta_generic_to_shared(SK);
    const unsigned svt_b = (unsigned)__cvta_generic_to_shared(SVT);
    const unsigned sp_b  = (unsigned)__cvta_generic_to_shared(SP);

    // non-trans b-frag lanes: rows +8 for lanes>=16, k-ext for lanes 8-15/24-31
    const int rowB = ((lane >> 4) << 3) + (lane & 7);
    const int khB  = ((lane >> 3) & 1) * 8;
    // a-frag lanes
    const int rowA16 = lane & 15, khA = (lane >> 4) * 8;

    const unsigned qk_base = sk_b  + (unsigned)(rowB * RB + khB * 2);
    const unsigned pvb_base = svt_b + (unsigned)(rowB * RB + khB * 2);
    const unsigned pva_base = sp_b + (unsigned)((wid * 16 + rowA16) * RB + khA * 2);

    auto issue = [&](int kt) {
        const int bf = kt & 1, kbase = kt * 64;
        const __half* Kp = g_K + (size_t)(b * SEQ + kbase) * HD;
#pragma unroll
        for (int l = 0; l < 4; l++) {
            int fid = tid + l * 128; int row = fid >> 3, c4 = fid & 7;
            cp16(&SK[bf * TW + row * 36 + c4 * 4], Kp + row * HD + c4 * 8);
            cp16(&SVT[bf * TW + row * 36 + c4 * 4],
                 g_Vt + (size_t)row * MTOT + b * SEQ + kbase + c4 * 8);
        }
        asm volatile("cp.async.commit_group;\n");
    };

    issue(0);

    // Q A-fragments in registers
    unsigned q[4][4];
    {
        const __half* Q0 = g_Q + (size_t)(b * SEQ + r0) * EMB + h * HD;
        const __half* Q1 = g_Q + (size_t)(b * SEQ + r1) * EMB + h * HD;
#pragma unroll
        for (int kc = 0; kc < 4; kc++) {
            q[kc][0] = *(const unsigned*)(Q0 + kc * 16 + 2 * tig);
            q[kc][1] = *(const unsigned*)(Q1 + kc * 16 + 2 * tig);
            q[kc][2] = *(const unsigned*)(Q0 + kc * 16 + 2 * tig + 8);
            q[kc][3] = *(const unsigned*)(Q1 + kc * 16 + 2 * tig + 8);
        }
    }

    float l0 = 0.f, l1 = 0.f;
    float o[8][4];
#pragma unroll
    for (int nt = 0; nt < 8; nt++)
#pragma unroll
        for (int c = 0; c < 4; c++) o[nt][c] = 0.f;

    const float cs = 0.125f * 1.44269504f;  // scale * log2(e)

    for (int kt = 0; kt <= qt; kt++) {
        const int bf = kt & 1;
        const int kbase = kt * 64;

        __syncthreads();                // all reads of buf[bf^1] done
        if (kt < qt) {
            issue(kt + 1);
            asm volatile("cp.async.wait_group 1;\n");
        } else {
            asm volatile("cp.async.wait_group 0;\n");
        }
        __syncthreads();                // buf[bf] visible

        // S = Q K^T
        float s[8][4];
#pragma unroll
        for (int nt = 0; nt < 8; nt++)
#pragma unroll
            for (int c = 0; c < 4; c++) s[nt][c] = 0.f;

#pragma unroll
        for (int kc = 0; kc < 4; kc++) {
            unsigned bb[8][2];
#pragma unroll
            for (int np = 0; np < 4; np++)
                ldsm4(bb[np * 2][0], bb[np * 2][1], bb[np * 2 + 1][0], bb[np * 2 + 1][1],
                      qk_base + bf * TWB + np * 16 * RB + kc * 32);
#pragma unroll
            for (int nt = 0; nt < 8; nt++)
                mma16(s[nt], q[kc][0], q[kc][1], q[kc][2], q[kc][3],
                      bb[nt][0], bb[nt][1]);
        }

        // p = 2^(s*cs); masked -> 0; accumulate l per-thread
        if (kt == qt) {
#pragma unroll
            for (int nt = 0; nt < 8; nt++) {
                int c = kbase + nt * 8 + 2 * tig;
                s[nt][0] = (c     <= r0) ? exp2f(s[nt][0] * cs) : 0.f;
                s[nt][1] = (c + 1 <= r0) ? exp2f(s[nt][1] * cs) : 0.f;
                s[nt][2] = (c     <= r1) ? exp2f(s[nt][2] * cs) : 0.f;
                s[nt][3] = (c + 1 <= r1) ? exp2f(s[nt][3] * cs) : 0.f;
                l0 += s[nt][0] + s[nt][1];
                l1 += s[nt][2] + s[nt][3];
            }
        } else {
#pragma unroll
            for (int nt = 0; nt < 8; nt++) {
                s[nt][0] = exp2f(s[nt][0] * cs);
                s[nt][1] = exp2f(s[nt][1] * cs);
                s[nt][2] = exp2f(s[nt][2] * cs);
                s[nt][3] = exp2f(s[nt][3] * cs);
                l0 += s[nt][0] + s[nt][1];
                l1 += s[nt][2] + s[nt][3];
            }
        }

        // P (fp16) -> private buffer; warp-private rows only
#pragma unroll
        for (int nt = 0; nt < 8; nt++) {
            int rr = wid * 16 + g, wrd = nt * 4 + tig;
            *(__half2*)&SP[rr * 36 + wrd]       = __floats2half2_rn(s[nt][0], s[nt][1]);
            *(__half2*)&SP[(rr + 8) * 36 + wrd] = __floats2half2_rn(s[nt][2], s[nt][3]);
        }
        __syncwarp();

        // O += P V
#pragma unroll
        for (int kc = 0; kc < 4; kc++) {
            unsigned a0, a1, a2, a3;
            ldsm4(a0, a1, a2, a3, pva_base + kc * 32);
            unsigned bb[8][2];
#pragma unroll
            for (int np = 0; np < 4; np++)
                ldsm4(bb[np * 2][0], bb[np * 2][1], bb[np * 2 + 1][0], bb[np * 2 + 1][1],
                      pvb_base + bf * TWB + np * 16 * RB + kc * 32);
#pragma unroll
            for (int nt = 0; nt < 8; nt++)
                mma16(o[nt], a0, a1, a2, a3, bb[nt][0], bb[nt][1]);
        }
    }

    // epilogue
    l0 += __shfl_xor_sync(0xffffffffu, l0, 1);
    l0 += __shfl_xor_sync(0xffffffffu, l0, 2);
    l1 += __shfl_xor_sync(0xffffffffu, l1, 1);
    l1 += __shfl_xor_sync(0xffffffffu, l1, 2);
    float i0 = 1.f / l0, i1 = 1.f / l1;
    float* Op = out + (size_t)b * SEQ * EMB + h * HD;
#pragma unroll
    for (int nt = 0; nt < 8; nt++) {
        int c = nt * 8 + 2 * tig;
        *(float2*)&Op[(size_t)r0 * EMB + c] = make_float2(o[nt][0] * i0, o[nt][1] * i0);
        *(float2*)&Op[(size_t)r1 * EMB + c] = make_float2(o[nt][2] * i1, o[nt][3] * i1);
    }
}

// ---------------------------------------------------------------------------
extern "C" void kernel_launch(void* const* d_in, const int* in_sizes, int n_in,
                              void* d_out, int out_size)
{
    (void)in_sizes; (void)n_in; (void)out_size;
    const float* X  = (const float*)d_in[0];
    const float* Wq = (const float*)d_in[1];
    const float* Wk = (const float*)d_in[2];
    const float* Wv = (const float*)d_in[3];
    float* out = (float*)d_out;

    static bool attr_set = false;
    if (!attr_set) {
        cudaFuncSetAttribute(attn_mma, cudaFuncAttributeMaxDynamicSharedMemorySize, ATTN_SMEM);
        attr_set = true;
    }

    qkv_gemm<<<dim3(18, MTOT / 128), 256>>>(X, Wq, Wk, Wv);
    attn_mma<<<dim3(SEQ / 64, NH, BATCH), 128, ATTN_SMEM>>>(out);
}

// round 11
// speedup vs baseline: 2.6369x; 1.2486x over previous
#include <cuda_runtime.h>
#include <cuda_fp16.h>

#define BATCH 2
#define SEQ   2048
#define EMB   1024
#define NH    16
#define HD    64
#define MTOT  (BATCH * SEQ)   // 4096

// fp16 copies of inputs (converted once per launch)
__device__ __half g_Xh[(size_t)MTOT * EMB];
__device__ __half g_Wqh[(size_t)EMB * EMB];
__device__ __half g_Wkh[(size_t)EMB * HD];
__device__ __half g_Wvh[(size_t)EMB * HD];
// Projected operands (fp16)
__device__ __half g_Q[(size_t)MTOT * EMB];    // [token][emb]
__device__ __half g_K[(size_t)MTOT * HD];     // [token][d]
__device__ __half g_Vt[(size_t)HD * MTOT];    // [d][token]

__device__ __forceinline__ void cp16(void* dst_smem, const void* src) {
    unsigned d = (unsigned)__cvta_generic_to_shared(dst_smem);
    asm volatile("cp.async.cg.shared.global [%0], [%1], 16;\n" :: "r"(d), "l"(src));
}

__device__ __forceinline__ void mma16(float* d, unsigned a0, unsigned a1,
                                      unsigned a2, unsigned a3,
                                      unsigned b0, unsigned b1) {
    asm volatile("mma.sync.aligned.m16n8k16.row.col.f32.f16.f16.f32 "
        "{%0,%1,%2,%3},{%4,%5,%6,%7},{%8,%9},{%0,%1,%2,%3};"
        : "+f"(d[0]), "+f"(d[1]), "+f"(d[2]), "+f"(d[3])
        : "r"(a0), "r"(a1), "r"(a2), "r"(a3), "r"(b0), "r"(b1));
}

__device__ __forceinline__ void ldsm4(unsigned& r0, unsigned& r1, unsigned& r2,
                                      unsigned& r3, unsigned addr) {
    asm volatile("ldmatrix.sync.aligned.m8n8.x4.shared.b16 {%0,%1,%2,%3}, [%4];"
        : "=r"(r0), "=r"(r1), "=r"(r2), "=r"(r3) : "r"(addr));
}
__device__ __forceinline__ void ldsm4t(unsigned& r0, unsigned& r1, unsigned& r2,
                                       unsigned& r3, unsigned addr) {
    asm volatile("ldmatrix.sync.aligned.m8n8.x4.trans.shared.b16 {%0,%1,%2,%3}, [%4];"
        : "=r"(r0), "=r"(r1), "=r"(r2), "=r"(r3) : "r"(addr));
}

#define RB 144   // row pitch bytes (72 halves)

// ---------------------------------------------------------------------------
// fp32 -> fp16 bulk convert (vectorized, grid-strided)
// ---------------------------------------------------------------------------
__global__ __launch_bounds__(256) void f2h(const float* __restrict__ src,
                                           __half* __restrict__ dst, int n4)
{
    int i = blockIdx.x * blockDim.x + threadIdx.x;
    int stride = gridDim.x * blockDim.x;
    for (; i < n4; i += stride) {
        float4 v = ((const float4*)src)[i];
        __half2 h0 = __floats2half2_rn(v.x, v.y);
        __half2 h1 = __floats2half2_rn(v.z, v.w);
        ((uint2*)dst)[i] = make_uint2(*(unsigned*)&h0, *(unsigned*)&h1);
    }
}

// ---------------------------------------------------------------------------
// Fused QKV projection GEMM, fp16 + LDSM + cp.async double buffering.
// BM=128, BN=64, BK=64. blockIdx.x: 0..15 Q blocks; 16 K; 17 V (transposed).
// ---------------------------------------------------------------------------
#define AW (128 * 72)   // halves per A buffer
#define BW (64 * 72)    // halves per B buffer
#define QKV_SMEM ((2 * AW + 2 * BW) * 2)

__global__ __launch_bounds__(256) void qkv_gemm()
{
    extern __shared__ __align__(16) __half smh[];
    __half* SA = smh;                 // [2][128][72]
    __half* SB = smh + 2 * AW;        // [2][64][72]

    const int nb = blockIdx.x;
    const int m0 = blockIdx.y * 128;

    const __half* W; int ldw, wc0;
    if (nb < 16)      { W = g_Wqh; ldw = EMB; wc0 = nb * 64; }
    else if (nb == 16){ W = g_Wkh; ldw = HD;  wc0 = 0; }
    else              { W = g_Wvh; ldw = HD;  wc0 = 0; }

    const int tid = threadIdx.x;
    const int wid = tid >> 5, lane = tid & 31;
    const int g = lane >> 2, tig = lane & 3;
    const int wm = wid >> 1, wn = wid & 1;

    const unsigned sa_b = (unsigned)__cvta_generic_to_shared(SA);
    const unsigned sb_b = (unsigned)__cvta_generic_to_shared(SB);

    const int rowA16 = lane & 15, khA = (lane >> 4) * 8;
    const int rowT = (lane & 7) + (((lane >> 3) & 1) * 8);
    const int colT = (lane >> 4) * 8;

    const unsigned a_base = sa_b + (unsigned)((wm * 32 + rowA16) * RB + khA * 2);
    const unsigned b_base = sb_b + (unsigned)(rowT * RB + (wn * 32 + colT) * 2);

    auto issue = [&](int it) {
        const int bf = it & 1, k0 = it * 64;
        // A tile 128x64 halves: 1024 x 16B, 4 per thread
#pragma unroll
        for (int l = 0; l < 4; l++) {
            int fid = tid + l * 256; int row = fid >> 3, c8 = fid & 7;
            cp16(&SA[bf * AW + row * 72 + c8 * 8],
                 g_Xh + (size_t)(m0 + row) * EMB + k0 + c8 * 8);
        }
        // B tile 64x64 halves: 512 x 16B, 2 per thread
#pragma unroll
        for (int l = 0; l < 2; l++) {
            int fid = tid + l * 256; int row = fid >> 3, c8 = fid & 7;
            cp16(&SB[bf * BW + row * 72 + c8 * 8],
                 W + (size_t)(k0 + row) * ldw + wc0 + c8 * 8);
        }
        asm volatile("cp.async.commit_group;\n");
    };

    issue(0);

    float acc[2][4][4];
#pragma unroll
    for (int mt = 0; mt < 2; mt++)
#pragma unroll
        for (int nt = 0; nt < 4; nt++)
#pragma unroll
            for (int c = 0; c < 4; c++) acc[mt][nt][c] = 0.f;

    for (int it = 0; it < 16; it++) {
        const int bf = it & 1;
        __syncthreads();               // reads of buf[bf^1] (iter it-1) done
        if (it + 1 < 16) {
            issue(it + 1);
            asm volatile("cp.async.wait_group 1;\n");
        } else {
            asm volatile("cp.async.wait_group 0;\n");
        }
        __syncthreads();               // buf[bf] visible

        const unsigned abf = a_base + bf * AW * 2;
        const unsigned bbf = b_base + bf * BW * 2;
#pragma unroll
        for (int kc = 0; kc < 4; kc++) {
            unsigned a[2][4], bb[4][2];
#pragma unroll
            for (int mt = 0; mt < 2; mt++)
                ldsm4(a[mt][0], a[mt][1], a[mt][2], a[mt][3],
                      abf + mt * 16 * RB + kc * 32);
#pragma unroll
            for (int np = 0; np < 2; np++)
                ldsm4t(bb[np * 2][0], bb[np * 2][1], bb[np * 2 + 1][0], bb[np * 2 + 1][1],
                       bbf + kc * 16 * RB + np * 32);
#pragma unroll
            for (int mt = 0; mt < 2; mt++)
#pragma unroll
                for (int nt = 0; nt < 4; nt++)
                    mma16(acc[mt][nt], a[mt][0], a[mt][1], a[mt][2], a[mt][3],
                          bb[nt][0], bb[nt][1]);
        }
    }

#pragma unroll
    for (int mt = 0; mt < 2; mt++) {
        int r0 = m0 + wm * 32 + mt * 16 + g;
        int r1 = r0 + 8;
#pragma unroll
        for (int nt = 0; nt < 4; nt++) {
            int c = wn * 32 + nt * 8 + 2 * tig;
            __half2 h0 = __floats2half2_rn(acc[mt][nt][0], acc[mt][nt][1]);
            __half2 h1 = __floats2half2_rn(acc[mt][nt][2], acc[mt][nt][3]);
            if (nb < 16) {
                int cc = nb * 64 + c;
                *(__half2*)&g_Q[(size_t)r0 * EMB + cc] = h0;
                *(__half2*)&g_Q[(size_t)r1 * EMB + cc] = h1;
            } else if (nb == 16) {
                *(__half2*)&g_K[(size_t)r0 * HD + c] = h0;
                *(__half2*)&g_K[(size_t)r1 * HD + c] = h1;
            } else {
                g_Vt[(size_t)c       * MTOT + r0] = __low2half(h0);
                g_Vt[(size_t)(c + 1) * MTOT + r0] = __high2half(h0);
                g_Vt[(size_t)c       * MTOT + r1] = __low2half(h1);
                g_Vt[(size_t)(c + 1) * MTOT + r1] = __high2half(h1);
            }
        }
    }
}

// ---------------------------------------------------------------------------
// Flash attention (unchanged from R10): fp16 m16n8k16, LDSM, cp.async.
// ---------------------------------------------------------------------------
#define TW (64 * 36)
#define TWB (64 * RB)
#define ATTN_SMEM (5 * TW * 4)

__global__ __launch_bounds__(128) void attn_mma(float* __restrict__ out)
{
    extern __shared__ __align__(16) unsigned smem_dyn[];
    unsigned* SK  = smem_dyn;
    unsigned* SVT = smem_dyn + 2 * TW;
    unsigned* SP  = smem_dyn + 4 * TW;

    const int qt = gridDim.x - 1 - blockIdx.x;
    const int h  = blockIdx.y;
    const int b  = blockIdx.z;
    const int qbase = qt * 64;

    const int tid = threadIdx.x;
    const int wid = tid >> 5, lane = tid & 31;
    const int g = lane >> 2, tig = lane & 3;

    const int r0 = qbase + wid * 16 + g;
    const int r1 = r0 + 8;

    const unsigned sk_b  = (unsigned)__cvta_generic_to_shared(SK);
    const unsigned svt_b = (unsigned)__cvta_generic_to_shared(SVT);
    const unsigned sp_b  = (unsigned)__cvta_generic_to_shared(SP);

    const int rowB = ((lane >> 4) << 3) + (lane & 7);
    const int khB  = ((lane >> 3) & 1) * 8;
    const int rowA16 = lane & 15, khA = (lane >> 4) * 8;

    const unsigned qk_base  = sk_b  + (unsigned)(rowB * RB + khB * 2);
    const unsigned pvb_base = svt_b + (unsigned)(rowB * RB + khB * 2);
    const unsigned pva_base = sp_b  + (unsigned)((wid * 16 + rowA16) * RB + khA * 2);

    auto issue = [&](int kt) {
        const int bf = kt & 1, kbase = kt * 64;
        const __half* Kp = g_K + (size_t)(b * SEQ + kbase) * HD;
#pragma unroll
        for (int l = 0; l < 4; l++) {
            int fid = tid + l * 128; int row = fid >> 3, c4 = fid & 7;
            cp16(&SK[bf * TW + row * 36 + c4 * 4], Kp + row * HD + c4 * 8);
            cp16(&SVT[bf * TW + row * 36 + c4 * 4],
                 g_Vt + (size_t)row * MTOT + b * SEQ + kbase + c4 * 8);
        }
        asm volatile("cp.async.commit_group;\n");
    };

    issue(0);

    unsigned q[4][4];
    {
        const __half* Q0 = g_Q + (size_t)(b * SEQ + r0) * EMB + h * HD;
        const __half* Q1 = g_Q + (size_t)(b * SEQ + r1) * EMB + h * HD;
#pragma unroll
        for (int kc = 0; kc < 4; kc++) {
            q[kc][0] = *(const unsigned*)(Q0 + kc * 16 + 2 * tig);
            q[kc][1] = *(const unsigned*)(Q1 + kc * 16 + 2 * tig);
            q[kc][2] = *(const unsigned*)(Q0 + kc * 16 + 2 * tig + 8);
            q[kc][3] = *(const unsigned*)(Q1 + kc * 16 + 2 * tig + 8);
        }
    }

    float l0 = 0.f, l1 = 0.f;
    float o[8][4];
#pragma unroll
    for (int nt = 0; nt < 8; nt++)
#pragma unroll
        for (int c = 0; c < 4; c++) o[nt][c] = 0.f;

    const float cs = 0.125f * 1.44269504f;

    for (int kt = 0; kt <= qt; kt++) {
        const int bf = kt & 1;
        const int kbase = kt * 64;

        __syncthreads();
        if (kt < qt) {
            issue(kt + 1);
            asm volatile("cp.async.wait_group 1;\n");
        } else {
            asm volatile("cp.async.wait_group 0;\n");
        }
        __syncthreads();

        float s[8][4];
#pragma unroll
        for (int nt = 0; nt < 8; nt++)
#pragma unroll
            for (int c = 0; c < 4; c++) s[nt][c] = 0.f;

#pragma unroll
        for (int kc = 0; kc < 4; kc++) {
            unsigned bb[8][2];
#pragma unroll
            for (int np = 0; np < 4; np++)
                ldsm4(bb[np * 2][0], bb[np * 2][1], bb[np * 2 + 1][0], bb[np * 2 + 1][1],
                      qk_base + bf * TWB + np * 16 * RB + kc * 32);
#pragma unroll
            for (int nt = 0; nt < 8; nt++)
                mma16(s[nt], q[kc][0], q[kc][1], q[kc][2], q[kc][3],
                      bb[nt][0], bb[nt][1]);
        }

        if (kt == qt) {
#pragma unroll
            for (int nt = 0; nt < 8; nt++) {
                int c = kbase + nt * 8 + 2 * tig;
                s[nt][0] = (c     <= r0) ? exp2f(s[nt][0] * cs) : 0.f;
                s[nt][1] = (c + 1 <= r0) ? exp2f(s[nt][1] * cs) : 0.f;
                s[nt][2] = (c     <= r1) ? exp2f(s[nt][2] * cs) : 0.f;
                s[nt][3] = (c + 1 <= r1) ? exp2f(s[nt][3] * cs) : 0.f;
                l0 += s[nt][0] + s[nt][1];
                l1 += s[nt][2] + s[nt][3];
            }
        } else {
#pragma unroll
            for (int nt = 0; nt < 8; nt++) {
                s[nt][0] = exp2f(s[nt][0] * cs);
                s[nt][1] = exp2f(s[nt][1] * cs);
                s[nt][2] = exp2f(s[nt][2] * cs);
                s[nt][3] = exp2f(s[nt][3] * cs);
                l0 += s[nt][0] + s[nt][1];
                l1 += s[nt][2] + s[nt][3];
            }
        }

#pragma unroll
        for (int nt = 0; nt < 8; nt++) {
            int rr = wid * 16 + g, wrd = nt * 4 + tig;
            *(__half2*)&SP[rr * 36 + wrd]       = __floats2half2_rn(s[nt][0], s[nt][1]);
            *(__half2*)&SP[(rr + 8) * 36 + wrd] = __floats2half2_rn(s[nt][2], s[nt][3]);
        }
        __syncwarp();

#pragma unroll
        for (int kc = 0; kc < 4; kc++) {
            unsigned a0, a1, a2, a3;
            ldsm4(a0, a1, a2, a3, pva_base + kc * 32);
            unsigned bb[8][2];
#pragma unroll
            for (int np = 0; np < 4; np++)
                ldsm4(bb[np * 2][0], bb[np * 2][1], bb[np * 2 + 1][0], bb[np * 2 + 1][1],
                      pvb_base + bf * TWB + np * 16 * RB + kc * 32);
#pragma unroll
            for (int nt = 0; nt < 8; nt++)
                mma16(o[nt], a0, a1, a2, a3, bb[nt][0], bb[nt][1]);
        }
    }

    l0 += __shfl_xor_sync(0xffffffffu, l0, 1);
    l0 += __shfl_xor_sync(0xffffffffu, l0, 2);
    l1 += __shfl_xor_sync(0xffffffffu, l1, 1);
    l1 += __shfl_xor_sync(0xffffffffu, l1, 2);
    float i0 = 1.f / l0, i1 = 1.f / l1;
    float* Op = out + (size_t)b * SEQ * EMB + h * HD;
#pragma unroll
    for (int nt = 0; nt < 8; nt++) {
        int c = nt * 8 + 2 * tig;
        *(float2*)&Op[(size_t)r0 * EMB + c] = make_float2(o[nt][0] * i0, o[nt][1] * i0);
        *(float2*)&Op[(size_t)r1 * EMB + c] = make_float2(o[nt][2] * i1, o[nt][3] * i1);
    }
}

// ---------------------------------------------------------------------------
extern "C" void kernel_launch(void* const* d_in, const int* in_sizes, int n_in,
                              void* d_out, int out_size)
{
    (void)in_sizes; (void)n_in; (void)out_size;
    const float* X  = (const float*)d_in[0];
    const float* Wq = (const float*)d_in[1];
    const float* Wk = (const float*)d_in[2];
    const float* Wv = (const float*)d_in[3];
    float* out = (float*)d_out;

    static bool attr_set = false;
    if (!attr_set) {
        cudaFuncSetAttribute(attn_mma, cudaFuncAttributeMaxDynamicSharedMemorySize, ATTN_SMEM);
        cudaFuncSetAttribute(qkv_gemm, cudaFuncAttributeMaxDynamicSharedMemorySize, QKV_SMEM);
        attr_set = true;
    }

    __half *Xh, *Wqh, *Wkh, *Wvh;
    cudaGetSymbolAddress((void**)&Xh,  g_Xh);
    cudaGetSymbolAddress((void**)&Wqh, g_Wqh);
    cudaGetSymbolAddress((void**)&Wkh, g_Wkh);
    cudaGetSymbolAddress((void**)&Wvh, g_Wvh);

    f2h<<<512, 256>>>(X,  Xh,  MTOT * EMB / 4);
    f2h<<<256, 256>>>(Wq, Wqh, EMB * EMB / 4);
    f2h<<<64,  256>>>(Wk, Wkh, EMB * HD / 4);
    f2h<<<64,  256>>>(Wv, Wvh, EMB * HD / 4);

    qkv_gemm<<<dim3(18, MTOT / 128), 256, QKV_SMEM>>>();
    attn_mma<<<dim3(SEQ / 64, NH, BATCH), 128, ATTN_SMEM>>>(out);
}

// round 12
// speedup vs baseline: 2.8336x; 1.0746x over previous
#include <cuda_runtime.h>
#include <cuda_fp16.h>

#define BATCH 2
#define SEQ   2048
#define EMB   1024
#define NH    16
#define HD    64
#define MTOT  (BATCH * SEQ)   // 4096

// fp16 copies of inputs (converted once per launch; Wq pre-scaled by 0.125*log2e)
__device__ __half g_Xh[(size_t)MTOT * EMB];
__device__ __half g_Wqh[(size_t)EMB * EMB];
__device__ __half g_Wkh[(size_t)EMB * HD];
__device__ __half g_Wvh[(size_t)EMB * HD];
// Projected operands (fp16). Q is pre-scaled (via Wq) so S = log2-domain scores.
__device__ __half g_Q[(size_t)MTOT * EMB];
__device__ __half g_K[(size_t)MTOT * HD];
__device__ __half g_Vt[(size_t)HD * MTOT];

__device__ __forceinline__ void cp16(void* dst_smem, const void* src) {
    unsigned d = (unsigned)__cvta_generic_to_shared(dst_smem);
    asm volatile("cp.async.cg.shared.global [%0], [%1], 16;\n" :: "r"(d), "l"(src));
}

__device__ __forceinline__ void mma16(float* d, unsigned a0, unsigned a1,
                                      unsigned a2, unsigned a3,
                                      unsigned b0, unsigned b1) {
    asm volatile("mma.sync.aligned.m16n8k16.row.col.f32.f16.f16.f32 "
        "{%0,%1,%2,%3},{%4,%5,%6,%7},{%8,%9},{%0,%1,%2,%3};"
        : "+f"(d[0]), "+f"(d[1]), "+f"(d[2]), "+f"(d[3])
        : "r"(a0), "r"(a1), "r"(a2), "r"(a3), "r"(b0), "r"(b1));
}

__device__ __forceinline__ void ldsm4(unsigned& r0, unsigned& r1, unsigned& r2,
                                      unsigned& r3, unsigned addr) {
    asm volatile("ldmatrix.sync.aligned.m8n8.x4.shared.b16 {%0,%1,%2,%3}, [%4];"
        : "=r"(r0), "=r"(r1), "=r"(r2), "=r"(r3) : "r"(addr));
}
__device__ __forceinline__ void ldsm4t(unsigned& r0, unsigned& r1, unsigned& r2,
                                       unsigned& r3, unsigned addr) {
    asm volatile("ldmatrix.sync.aligned.m8n8.x4.trans.shared.b16 {%0,%1,%2,%3}, [%4];"
        : "=r"(r0), "=r"(r1), "=r"(r2), "=r"(r3) : "r"(addr));
}
__device__ __forceinline__ void stsm4(unsigned addr, unsigned r0, unsigned r1,
                                      unsigned r2, unsigned r3) {
    asm volatile("stmatrix.sync.aligned.m8n8.x4.shared.b16 [%0], {%1,%2,%3,%4};"
        :: "r"(addr), "r"(r0), "r"(r1), "r"(r2), "r"(r3));
}

#define RB 144   // row pitch bytes (72 halves)

// ---------------------------------------------------------------------------
// Fused fp32 -> fp16 convert of all four inputs (Wq scaled by 0.125*log2e).
// ---------------------------------------------------------------------------
#define N1 (MTOT * EMB / 4)
#define N2 (EMB * EMB / 4)
#define N3 (EMB * HD / 4)

__global__ __launch_bounds__(256) void f2h_all(
    const float* __restrict__ X, const float* __restrict__ Wq,
    const float* __restrict__ Wk, const float* __restrict__ Wv)
{
    const float cs = 0.125f * 1.44269504f;
    int i = blockIdx.x * blockDim.x + threadIdx.x;
    int stride = gridDim.x * blockDim.x;
    const int total = N1 + N2 + 2 * N3;
    for (; i < total; i += stride) {
        const float4* src; uint2* dst; int j; float sc = 1.f;
        if (i < N1)                { src = (const float4*)X;  dst = (uint2*)g_Xh;  j = i; }
        else if (i < N1 + N2)      { src = (const float4*)Wq; dst = (uint2*)g_Wqh; j = i - N1; sc = cs; }
        else if (i < N1 + N2 + N3) { src = (const float4*)Wk; dst = (uint2*)g_Wkh; j = i - N1 - N2; }
        else                       { src = (const float4*)Wv; dst = (uint2*)g_Wvh; j = i - N1 - N2 - N3; }
        float4 v = src[j];
        __half2 h0 = __floats2half2_rn(v.x * sc, v.y * sc);
        __half2 h1 = __floats2half2_rn(v.z * sc, v.w * sc);
        dst[j] = make_uint2(*(unsigned*)&h0, *(unsigned*)&h1);
    }
}

// ---------------------------------------------------------------------------
// Fused QKV projection GEMM, fp16 + LDSM + cp.async (unchanged from R11).
// ---------------------------------------------------------------------------
#define AW (128 * 72)
#define BW (64 * 72)
#define QKV_SMEM ((2 * AW + 2 * BW) * 2)

__global__ __launch_bounds__(256) void qkv_gemm()
{
    extern __shared__ __align__(16) __half smh[];
    __half* SA = smh;
    __half* SB = smh + 2 * AW;

    const int nb = blockIdx.x;
    const int m0 = blockIdx.y * 128;

    const __half* W; int ldw, wc0;
    if (nb < 16)      { W = g_Wqh; ldw = EMB; wc0 = nb * 64; }
    else if (nb == 16){ W = g_Wkh; ldw = HD;  wc0 = 0; }
    else              { W = g_Wvh; ldw = HD;  wc0 = 0; }

    const int tid = threadIdx.x;
    const int wid = tid >> 5, lane = tid & 31;
    const int g = lane >> 2, tig = lane & 3;
    const int wm = wid >> 1, wn = wid & 1;

    const unsigned sa_b = (unsigned)__cvta_generic_to_shared(SA);
    const unsigned sb_b = (unsigned)__cvta_generic_to_shared(SB);

    const int rowA16 = lane & 15, khA = (lane >> 4) * 8;
    const int rowT = (lane & 7) + (((lane >> 3) & 1) * 8);
    const int colT = (lane >> 4) * 8;

    const unsigned a_base = sa_b + (unsigned)((wm * 32 + rowA16) * RB + khA * 2);
    const unsigned b_base = sb_b + (unsigned)(rowT * RB + (wn * 32 + colT) * 2);

    auto issue = [&](int it) {
        const int bf = it & 1, k0 = it * 64;
#pragma unroll
        for (int l = 0; l < 4; l++) {
            int fid = tid + l * 256; int row = fid >> 3, c8 = fid & 7;
            cp16(&SA[bf * AW + row * 72 + c8 * 8],
                 g_Xh + (size_t)(m0 + row) * EMB + k0 + c8 * 8);
        }
#pragma unroll
        for (int l = 0; l < 2; l++) {
            int fid = tid + l * 256; int row = fid >> 3, c8 = fid & 7;
            cp16(&SB[bf * BW + row * 72 + c8 * 8],
                 W + (size_t)(k0 + row) * ldw + wc0 + c8 * 8);
        }
        asm volatile("cp.async.commit_group;\n");
    };

    issue(0);

    float acc[2][4][4];
#pragma unroll
    for (int mt = 0; mt < 2; mt++)
#pragma unroll
        for (int nt = 0; nt < 4; nt++)
#pragma unroll
            for (int c = 0; c < 4; c++) acc[mt][nt][c] = 0.f;

    for (int it = 0; it < 16; it++) {
        const int bf = it & 1;
        __syncthreads();
        if (it + 1 < 16) {
            issue(it + 1);
            asm volatile("cp.async.wait_group 1;\n");
        } else {
            asm volatile("cp.async.wait_group 0;\n");
        }
        __syncthreads();

        const unsigned abf = a_base + bf * AW * 2;
        const unsigned bbf = b_base + bf * BW * 2;
#pragma unroll
        for (int kc = 0; kc < 4; kc++) {
            unsigned a[2][4], bb[4][2];
#pragma unroll
            for (int mt = 0; mt < 2; mt++)
                ldsm4(a[mt][0], a[mt][1], a[mt][2], a[mt][3],
                      abf + mt * 16 * RB + kc * 32);
#pragma unroll
            for (int np = 0; np < 2; np++)
                ldsm4t(bb[np * 2][0], bb[np * 2][1], bb[np * 2 + 1][0], bb[np * 2 + 1][1],
                       bbf + kc * 16 * RB + np * 32);
#pragma unroll
            for (int mt = 0; mt < 2; mt++)
#pragma unroll
                for (int nt = 0; nt < 4; nt++)
                    mma16(acc[mt][nt], a[mt][0], a[mt][1], a[mt][2], a[mt][3],
                          bb[nt][0], bb[nt][1]);
        }
    }

#pragma unroll
    for (int mt = 0; mt < 2; mt++) {
        int r0 = m0 + wm * 32 + mt * 16 + g;
        int r1 = r0 + 8;
#pragma unroll
        for (int nt = 0; nt < 4; nt++) {
            int c = wn * 32 + nt * 8 + 2 * tig;
            __half2 h0 = __floats2half2_rn(acc[mt][nt][0], acc[mt][nt][1]);
            __half2 h1 = __floats2half2_rn(acc[mt][nt][2], acc[mt][nt][3]);
            if (nb < 16) {
                int cc = nb * 64 + c;
                *(__half2*)&g_Q[(size_t)r0 * EMB + cc] = h0;
                *(__half2*)&g_Q[(size_t)r1 * EMB + cc] = h1;
            } else if (nb == 16) {
                *(__half2*)&g_K[(size_t)r0 * HD + c] = h0;
                *(__half2*)&g_K[(size_t)r1 * HD + c] = h1;
            } else {
                g_Vt[(size_t)c       * MTOT + r0] = __low2half(h0);
                g_Vt[(size_t)(c + 1) * MTOT + r0] = __high2half(h0);
                g_Vt[(size_t)c       * MTOT + r1] = __low2half(h1);
                g_Vt[(size_t)(c + 1) * MTOT + r1] = __high2half(h1);
            }
        }
    }
}

// ---------------------------------------------------------------------------
// Flash attention: fp16 m16n8k16, LDSM/STSM, cp.async double buffering.
// Q pre-scaled -> p = exp2(s). Row-sum l computed by a ones-column MMA.
// ---------------------------------------------------------------------------
#define TW (64 * 36)
#define TWB (64 * RB)
#define ATTN_SMEM (5 * TW * 4)
#define ONEH2 0x3C003C00u   // half2(1.0, 1.0)

__global__ __launch_bounds__(128) void attn_mma(float* __restrict__ out)
{
    extern __shared__ __align__(16) unsigned smem_dyn[];
    unsigned* SK  = smem_dyn;
    unsigned* SVT = smem_dyn + 2 * TW;
    unsigned* SP  = smem_dyn + 4 * TW;

    const int qt = gridDim.x - 1 - blockIdx.x;
    const int h  = blockIdx.y;
    const int b  = blockIdx.z;
    const int qbase = qt * 64;

    const int tid = threadIdx.x;
    const int wid = tid >> 5, lane = tid & 31;
    const int g = lane >> 2, tig = lane & 3;

    const int r0 = qbase + wid * 16 + g;
    const int r1 = r0 + 8;

    const unsigned sk_b  = (unsigned)__cvta_generic_to_shared(SK);
    const unsigned svt_b = (unsigned)__cvta_generic_to_shared(SVT);
    const unsigned sp_b  = (unsigned)__cvta_generic_to_shared(SP);

    const int rowB = ((lane >> 4) << 3) + (lane & 7);
    const int khB  = ((lane >> 3) & 1) * 8;
    const int rowA16 = lane & 15, khA = (lane >> 4) * 8;

    const unsigned qk_base  = sk_b  + (unsigned)(rowB * RB + khB * 2);
    const unsigned pvb_base = svt_b + (unsigned)(rowB * RB + khB * 2);
    const unsigned pva_base = sp_b  + (unsigned)((wid * 16 + rowA16) * RB + khA * 2);
    // stmatrix per-lane address: tile t=lane>>3 -> (rowblk t&1, colblk t>>1)
    const int st_t = lane >> 3, st_r = lane & 7;
    const unsigned sts_base = sp_b +
        (unsigned)((wid * 16 + (st_t & 1) * 8 + st_r) * RB + (st_t >> 1) * 16);

    auto issue = [&](int kt) {
        const int bf = kt & 1, kbase = kt * 64;
        const __half* Kp = g_K + (size_t)(b * SEQ + kbase) * HD;
#pragma unroll
        for (int l = 0; l < 4; l++) {
            int fid = tid + l * 128; int row = fid >> 3, c4 = fid & 7;
            cp16(&SK[bf * TW + row * 36 + c4 * 4], Kp + row * HD + c4 * 8);
            cp16(&SVT[bf * TW + row * 36 + c4 * 4],
                 g_Vt + (size_t)row * MTOT + b * SEQ + kbase + c4 * 8);
        }
        asm volatile("cp.async.commit_group;\n");
    };

    issue(0);

    unsigned q[4][4];
    {
        const __half* Q0 = g_Q + (size_t)(b * SEQ + r0) * EMB + h * HD;
        const __half* Q1 = g_Q + (size_t)(b * SEQ + r1) * EMB + h * HD;
#pragma unroll
        for (int kc = 0; kc < 4; kc++) {
            q[kc][0] = *(const unsigned*)(Q0 + kc * 16 + 2 * tig);
            q[kc][1] = *(const unsigned*)(Q1 + kc * 16 + 2 * tig);
            q[kc][2] = *(const unsigned*)(Q0 + kc * 16 + 2 * tig + 8);
            q[kc][3] = *(const unsigned*)(Q1 + kc * 16 + 2 * tig + 8);
        }
    }

    float o[8][4], lacc[4];
#pragma unroll
    for (int nt = 0; nt < 8; nt++)
#pragma unroll
        for (int c = 0; c < 4; c++) o[nt][c] = 0.f;
#pragma unroll
    for (int c = 0; c < 4; c++) lacc[c] = 0.f;

    for (int kt = 0; kt <= qt; kt++) {
        const int bf = kt & 1;
        const int kbase = kt * 64;

        __syncthreads();
        if (kt < qt) {
            issue(kt + 1);
            asm volatile("cp.async.wait_group 1;\n");
        } else {
            asm volatile("cp.async.wait_group 0;\n");
        }
        __syncthreads();

        // S = Q K^T (already log2-domain: Q pre-scaled by 0.125*log2e)
        float s[8][4];
#pragma unroll
        for (int nt = 0; nt < 8; nt++)
#pragma unroll
            for (int c = 0; c < 4; c++) s[nt][c] = 0.f;

#pragma unroll
        for (int kc = 0; kc < 4; kc++) {
            unsigned bb[8][2];
#pragma unroll
            for (int np = 0; np < 4; np++)
                ldsm4(bb[np * 2][0], bb[np * 2][1], bb[np * 2 + 1][0], bb[np * 2 + 1][1],
                      qk_base + bf * TWB + np * 16 * RB + kc * 32);
#pragma unroll
            for (int nt = 0; nt < 8; nt++)
                mma16(s[nt], q[kc][0], q[kc][1], q[kc][2], q[kc][3],
                      bb[nt][0], bb[nt][1]);
        }

        // p = 2^s; masked -> 0. Pack to half2 fragments.
        unsigned ph[8][2];
        if (kt == qt) {
#pragma unroll
            for (int nt = 0; nt < 8; nt++) {
                int c = kbase + nt * 8 + 2 * tig;
                float p0 = (c     <= r0) ? exp2f(s[nt][0]) : 0.f;
                float p1 = (c + 1 <= r0) ? exp2f(s[nt][1]) : 0.f;
                float p2 = (c     <= r1) ? exp2f(s[nt][2]) : 0.f;
                float p3 = (c + 1 <= r1) ? exp2f(s[nt][3]) : 0.f;
                __half2 h0 = __floats2half2_rn(p0, p1);
                __half2 h1 = __floats2half2_rn(p2, p3);
                ph[nt][0] = *(unsigned*)&h0; ph[nt][1] = *(unsigned*)&h1;
            }
        } else {
#pragma unroll
            for (int nt = 0; nt < 8; nt++) {
                __half2 h0 = __floats2half2_rn(exp2f(s[nt][0]), exp2f(s[nt][1]));
                __half2 h1 = __floats2half2_rn(exp2f(s[nt][2]), exp2f(s[nt][3]));
                ph[nt][0] = *(unsigned*)&h0; ph[nt][1] = *(unsigned*)&h1;
            }
        }

        // P -> smem via stmatrix (warp-private rows)
#pragma unroll
        for (int ntb = 0; ntb < 8; ntb += 2)
            stsm4(sts_base + ntb * 16, ph[ntb][0], ph[ntb][1],
                  ph[ntb + 1][0], ph[ntb + 1][1]);
        __syncwarp();

        // O += P V ; l += P @ ones (free row-sum via constant b-frags)
#pragma unroll
        for (int kc = 0; kc < 4; kc++) {
            unsigned a0, a1, a2, a3;
            ldsm4(a0, a1, a2, a3, pva_base + kc * 32);
            unsigned bb[8][2];
#pragma unroll
            for (int np = 0; np < 4; np++)
                ldsm4(bb[np * 2][0], bb[np * 2][1], bb[np * 2 + 1][0], bb[np * 2 + 1][1],
                      pvb_base + bf * TWB + np * 16 * RB + kc * 32);
#pragma unroll
            for (int nt = 0; nt < 8; nt++)
                mma16(o[nt], a0, a1, a2, a3, bb[nt][0], bb[nt][1]);
            mma16(lacc, a0, a1, a2, a3, ONEH2, ONEH2);
        }
    }

    // epilogue: l row-sums already complete in lacc (no shuffles needed)
    float i0 = 1.f / lacc[0], i1 = 1.f / lacc[2];
    float* Op = out + (size_t)b * SEQ * EMB + h * HD;
#pragma unroll
    for (int nt = 0; nt < 8; nt++) {
        int c = nt * 8 + 2 * tig;
        *(float2*)&Op[(size_t)r0 * EMB + c] = make_float2(o[nt][0] * i0, o[nt][1] * i0);
        *(float2*)&Op[(size_t)r1 * EMB + c] = make_float2(o[nt][2] * i1, o[nt][3] * i1);
    }
}

// ---------------------------------------------------------------------------
extern "C" void kernel_launch(void* const* d_in, const int* in_sizes, int n_in,
                              void* d_out, int out_size)
{
    (void)in_sizes; (void)n_in; (void)out_size;
    const float* X  = (const float*)d_in[0];
    const float* Wq = (const float*)d_in[1];
    const float* Wk = (const float*)d_in[2];
    const float* Wv = (const float*)d_in[3];
    float* out = (float*)d_out;

    static bool attr_set = false;
    if (!attr_set) {
        cudaFuncSetAttribute(attn_mma, cudaFuncAttributeMaxDynamicSharedMemorySize, ATTN_SMEM);
        cudaFuncSetAttribute(qkv_gemm, cudaFuncAttributeMaxDynamicSharedMemorySize, QKV_SMEM);
        attr_set = true;
    }

    f2h_all<<<1024, 256>>>(X, Wq, Wk, Wv);
    qkv_gemm<<<dim3(18, MTOT / 128), 256, QKV_SMEM>>>();
    attn_mma<<<dim3(SEQ / 64, NH, BATCH), 128, ATTN_SMEM>>>(out);
}

// round 13
// speedup vs baseline: 2.9827x; 1.0526x over previous
#include <cuda_runtime.h>
#include <cuda_fp16.h>

#define BATCH 2
#define SEQ   2048
#define EMB   1024
#define NH    16
#define HD    64
#define MTOT  (BATCH * SEQ)   // 4096

// fp16 copies of inputs (converted once per launch; Wq pre-scaled by 0.125*log2e)
__device__ __half g_Xh[(size_t)MTOT * EMB];
__device__ __half g_Wqh[(size_t)EMB * EMB];
__device__ __half g_Wkh[(size_t)EMB * HD];
__device__ __half g_Wvh[(size_t)EMB * HD];
// Projected operands (fp16). Q pre-scaled (via Wq) -> S = log2-domain scores.
__device__ __half g_Q[(size_t)MTOT * EMB];
__device__ __half g_K[(size_t)MTOT * HD];
__device__ __half g_Vt[(size_t)HD * MTOT];

__device__ __forceinline__ void cp16(void* dst_smem, const void* src) {
    unsigned d = (unsigned)__cvta_generic_to_shared(dst_smem);
    asm volatile("cp.async.cg.shared.global [%0], [%1], 16;\n" :: "r"(d), "l"(src));
}

__device__ __forceinline__ void mma16(float* d, unsigned a0, unsigned a1,
                                      unsigned a2, unsigned a3,
                                      unsigned b0, unsigned b1) {
    asm volatile("mma.sync.aligned.m16n8k16.row.col.f32.f16.f16.f32 "
        "{%0,%1,%2,%3},{%4,%5,%6,%7},{%8,%9},{%0,%1,%2,%3};"
        : "+f"(d[0]), "+f"(d[1]), "+f"(d[2]), "+f"(d[3])
        : "r"(a0), "r"(a1), "r"(a2), "r"(a3), "r"(b0), "r"(b1));
}

__device__ __forceinline__ void ldsm4(unsigned& r0, unsigned& r1, unsigned& r2,
                                      unsigned& r3, unsigned addr) {
    asm volatile("ldmatrix.sync.aligned.m8n8.x4.shared.b16 {%0,%1,%2,%3}, [%4];"
        : "=r"(r0), "=r"(r1), "=r"(r2), "=r"(r3) : "r"(addr));
}
__device__ __forceinline__ void ldsm4t(unsigned& r0, unsigned& r1, unsigned& r2,
                                       unsigned& r3, unsigned addr) {
    asm volatile("ldmatrix.sync.aligned.m8n8.x4.trans.shared.b16 {%0,%1,%2,%3}, [%4];"
        : "=r"(r0), "=r"(r1), "=r"(r2), "=r"(r3) : "r"(addr));
}

#define RB 144   // row pitch bytes (72 halves)

// ---------------------------------------------------------------------------
// Fused fp32 -> fp16 convert of all inputs (Wq scaled by 0.125*log2e).
// ---------------------------------------------------------------------------
#define N1 (MTOT * EMB / 4)
#define N2 (EMB * EMB / 4)
#define N3 (EMB * HD / 4)

__global__ __launch_bounds__(256) void f2h_all(
    const float* __restrict__ X, const float* __restrict__ Wq,
    const float* __restrict__ Wk, const float* __restrict__ Wv)
{
    const float cs = 0.125f * 1.44269504f;
    int i = blockIdx.x * blockDim.x + threadIdx.x;
    int stride = gridDim.x * blockDim.x;
    const int total = N1 + N2 + 2 * N3;
    for (; i < total; i += stride) {
        const float4* src; uint2* dst; int j; float sc = 1.f;
        if (i < N1)                { src = (const float4*)X;  dst = (uint2*)g_Xh;  j = i; }
        else if (i < N1 + N2)      { src = (const float4*)Wq; dst = (uint2*)g_Wqh; j = i - N1; sc = cs; }
        else if (i < N1 + N2 + N3) { src = (const float4*)Wk; dst = (uint2*)g_Wkh; j = i - N1 - N2; }
        else                       { src = (const float4*)Wv; dst = (uint2*)g_Wvh; j = i - N1 - N2 - N3; }
        float4 v = src[j];
        __half2 h0 = __floats2half2_rn(v.x * sc, v.y * sc);
        __half2 h1 = __floats2half2_rn(v.z * sc, v.w * sc);
        dst[j] = make_uint2(*(unsigned*)&h0, *(unsigned*)&h1);
    }
}

// ---------------------------------------------------------------------------
// Fused QKV projection GEMM, fp16 + LDSM + cp.async (unchanged).
// ---------------------------------------------------------------------------
#define AW (128 * 72)
#define BW (64 * 72)
#define QKV_SMEM ((2 * AW + 2 * BW) * 2)

__global__ __launch_bounds__(256) void qkv_gemm()
{
    extern __shared__ __align__(16) __half smh[];
    __half* SA = smh;
    __half* SB = smh + 2 * AW;

    const int nb = blockIdx.x;
    const int m0 = blockIdx.y * 128;

    const __half* W; int ldw, wc0;
    if (nb < 16)      { W = g_Wqh; ldw = EMB; wc0 = nb * 64; }
    else if (nb == 16){ W = g_Wkh; ldw = HD;  wc0 = 0; }
    else              { W = g_Wvh; ldw = HD;  wc0 = 0; }

    const int tid = threadIdx.x;
    const int wid = tid >> 5, lane = tid & 31;
    const int g = lane >> 2, tig = lane & 3;
    const int wm = wid >> 1, wn = wid & 1;

    const unsigned sa_b = (unsigned)__cvta_generic_to_shared(SA);
    const unsigned sb_b = (unsigned)__cvta_generic_to_shared(SB);

    const int rowA16 = lane & 15, khA = (lane >> 4) * 8;
    const int rowT = (lane & 7) + (((lane >> 3) & 1) * 8);
    const int colT = (lane >> 4) * 8;

    const unsigned a_base = sa_b + (unsigned)((wm * 32 + rowA16) * RB + khA * 2);
    const unsigned b_base = sb_b + (unsigned)(rowT * RB + (wn * 32 + colT) * 2);

    auto issue = [&](int it) {
        const int bf = it & 1, k0 = it * 64;
#pragma unroll
        for (int l = 0; l < 4; l++) {
            int fid = tid + l * 256; int row = fid >> 3, c8 = fid & 7;
            cp16(&SA[bf * AW + row * 72 + c8 * 8],
                 g_Xh + (size_t)(m0 + row) * EMB + k0 + c8 * 8);
        }
#pragma unroll
        for (int l = 0; l < 2; l++) {
            int fid = tid + l * 256; int row = fid >> 3, c8 = fid & 7;
            cp16(&SB[bf * BW + row * 72 + c8 * 8],
                 W + (size_t)(k0 + row) * ldw + wc0 + c8 * 8);
        }
        asm volatile("cp.async.commit_group;\n");
    };

    issue(0);

    float acc[2][4][4];
#pragma unroll
    for (int mt = 0; mt < 2; mt++)
#pragma unroll
        for (int nt = 0; nt < 4; nt++)
#pragma unroll
            for (int c = 0; c < 4; c++) acc[mt][nt][c] = 0.f;

    for (int it = 0; it < 16; it++) {
        const int bf = it & 1;
        __syncthreads();
        if (it + 1 < 16) {
            issue(it + 1);
            asm volatile("cp.async.wait_group 1;\n");
        } else {
            asm volatile("cp.async.wait_group 0;\n");
        }
        __syncthreads();

        const unsigned abf = a_base + bf * AW * 2;
        const unsigned bbf = b_base + bf * BW * 2;
#pragma unroll
        for (int kc = 0; kc < 4; kc++) {
            unsigned a[2][4], bb[4][2];
#pragma unroll
            for (int mt = 0; mt < 2; mt++)
                ldsm4(a[mt][0], a[mt][1], a[mt][2], a[mt][3],
                      abf + mt * 16 * RB + kc * 32);
#pragma unroll
            for (int np = 0; np < 2; np++)
                ldsm4t(bb[np * 2][0], bb[np * 2][1], bb[np * 2 + 1][0], bb[np * 2 + 1][1],
                       bbf + kc * 16 * RB + np * 32);
#pragma unroll
            for (int mt = 0; mt < 2; mt++)
#pragma unroll
                for (int nt = 0; nt < 4; nt++)
                    mma16(acc[mt][nt], a[mt][0], a[mt][1], a[mt][2], a[mt][3],
                          bb[nt][0], bb[nt][1]);
        }
    }

#pragma unroll
    for (int mt = 0; mt < 2; mt++) {
        int r0 = m0 + wm * 32 + mt * 16 + g;
        int r1 = r0 + 8;
#pragma unroll
        for (int nt = 0; nt < 4; nt++) {
            int c = wn * 32 + nt * 8 + 2 * tig;
            __half2 h0 = __floats2half2_rn(acc[mt][nt][0], acc[mt][nt][1]);
            __half2 h1 = __floats2half2_rn(acc[mt][nt][2], acc[mt][nt][3]);
            if (nb < 16) {
                int cc = nb * 64 + c;
                *(__half2*)&g_Q[(size_t)r0 * EMB + cc] = h0;
                *(__half2*)&g_Q[(size_t)r1 * EMB + cc] = h1;
            } else if (nb == 16) {
                *(__half2*)&g_K[(size_t)r0 * HD + c] = h0;
                *(__half2*)&g_K[(size_t)r1 * HD + c] = h1;
            } else {
                g_Vt[(size_t)c       * MTOT + r0] = __low2half(h0);
                g_Vt[(size_t)(c + 1) * MTOT + r0] = __high2half(h0);
                g_Vt[(size_t)c       * MTOT + r1] = __low2half(h1);
                g_Vt[(size_t)(c + 1) * MTOT + r1] = __high2half(h1);
            }
        }
    }
}

// ---------------------------------------------------------------------------
// Flash attention: fp16 m16n8k16, P kept in registers (FA2-style fragment
// reuse: QK C-frag == PV A-frag layout). No P smem buffer at all.
// smem: K 2x + Vt 2x = 36 KB.
// ---------------------------------------------------------------------------
#define TW (64 * 36)
#define TWB (64 * RB)
#define ATTN_SMEM (4 * TW * 4)
#define ONEH2 0x3C003C00u   // half2(1.0, 1.0)

__global__ __launch_bounds__(128) void attn_mma(float* __restrict__ out)
{
    extern __shared__ __align__(16) unsigned smem_dyn[];
    unsigned* SK  = smem_dyn;
    unsigned* SVT = smem_dyn + 2 * TW;

    const int qt = gridDim.x - 1 - blockIdx.x;
    const int h  = blockIdx.y;
    const int b  = blockIdx.z;
    const int qbase = qt * 64;

    const int tid = threadIdx.x;
    const int wid = tid >> 5, lane = tid & 31;
    const int g = lane >> 2, tig = lane & 3;

    const int r0 = qbase + wid * 16 + g;
    const int r1 = r0 + 8;

    const unsigned sk_b  = (unsigned)__cvta_generic_to_shared(SK);
    const unsigned svt_b = (unsigned)__cvta_generic_to_shared(SVT);

    const int rowB = ((lane >> 4) << 3) + (lane & 7);
    const int khB  = ((lane >> 3) & 1) * 8;

    const unsigned qk_base  = sk_b  + (unsigned)(rowB * RB + khB * 2);
    const unsigned pvb_base = svt_b + (unsigned)(rowB * RB + khB * 2);

    auto issue = [&](int kt) {
        const int bf = kt & 1, kbase = kt * 64;
        const __half* Kp = g_K + (size_t)(b * SEQ + kbase) * HD;
#pragma unroll
        for (int l = 0; l < 4; l++) {
            int fid = tid + l * 128; int row = fid >> 3, c4 = fid & 7;
            cp16(&SK[bf * TW + row * 36 + c4 * 4], Kp + row * HD + c4 * 8);
            cp16(&SVT[bf * TW + row * 36 + c4 * 4],
                 g_Vt + (size_t)row * MTOT + b * SEQ + kbase + c4 * 8);
        }
        asm volatile("cp.async.commit_group;\n");
    };

    issue(0);

    unsigned q[4][4];
    {
        const __half* Q0 = g_Q + (size_t)(b * SEQ + r0) * EMB + h * HD;
        const __half* Q1 = g_Q + (size_t)(b * SEQ + r1) * EMB + h * HD;
#pragma unroll
        for (int kc = 0; kc < 4; kc++) {
            q[kc][0] = *(const unsigned*)(Q0 + kc * 16 + 2 * tig);
            q[kc][1] = *(const unsigned*)(Q1 + kc * 16 + 2 * tig);
            q[kc][2] = *(const unsigned*)(Q0 + kc * 16 + 2 * tig + 8);
            q[kc][3] = *(const unsigned*)(Q1 + kc * 16 + 2 * tig + 8);
        }
    }

    float o[8][4], lacc[4];
#pragma unroll
    for (int nt = 0; nt < 8; nt++)
#pragma unroll
        for (int c = 0; c < 4; c++) o[nt][c] = 0.f;
#pragma unroll
    for (int c = 0; c < 4; c++) lacc[c] = 0.f;

    for (int kt = 0; kt <= qt; kt++) {
        const int bf = kt & 1;
        const int kbase = kt * 64;

        __syncthreads();
        if (kt < qt) {
            issue(kt + 1);
            asm volatile("cp.async.wait_group 1;\n");
        } else {
            asm volatile("cp.async.wait_group 0;\n");
        }
        __syncthreads();

        // S = Q K^T (log2-domain; Q pre-scaled)
        float s[8][4];
#pragma unroll
        for (int nt = 0; nt < 8; nt++)
#pragma unroll
            for (int c = 0; c < 4; c++) s[nt][c] = 0.f;

#pragma unroll
        for (int kc = 0; kc < 4; kc++) {
            unsigned bb[8][2];
#pragma unroll
            for (int np = 0; np < 4; np++)
                ldsm4(bb[np * 2][0], bb[np * 2][1], bb[np * 2 + 1][0], bb[np * 2 + 1][1],
                      qk_base + bf * TWB + np * 16 * RB + kc * 32);
#pragma unroll
            for (int nt = 0; nt < 8; nt++)
                mma16(s[nt], q[kc][0], q[kc][1], q[kc][2], q[kc][3],
                      bb[nt][0], bb[nt][1]);
        }

        // p = 2^s; masked -> 0; pack straight into PV A-fragments.
        unsigned ph[8][2];
        if (kt == qt) {
#pragma unroll
            for (int nt = 0; nt < 8; nt++) {
                int c = kbase + nt * 8 + 2 * tig;
                float p0 = (c     <= r0) ? exp2f(s[nt][0]) : 0.f;
                float p1 = (c + 1 <= r0) ? exp2f(s[nt][1]) : 0.f;
                float p2 = (c     <= r1) ? exp2f(s[nt][2]) : 0.f;
                float p3 = (c + 1 <= r1) ? exp2f(s[nt][3]) : 0.f;
                __half2 h0 = __floats2half2_rn(p0, p1);
                __half2 h1 = __floats2half2_rn(p2, p3);
                ph[nt][0] = *(unsigned*)&h0; ph[nt][1] = *(unsigned*)&h1;
            }
        } else {
#pragma unroll
            for (int nt = 0; nt < 8; nt++) {
                __half2 h0 = __floats2half2_rn(exp2f(s[nt][0]), exp2f(s[nt][1]));
                __half2 h1 = __floats2half2_rn(exp2f(s[nt][2]), exp2f(s[nt][3]));
                ph[nt][0] = *(unsigned*)&h0; ph[nt][1] = *(unsigned*)&h1;
            }
        }

        // O += P V ; l += P @ ones. P A-frags come straight from ph:
        // k-chunk kc: a0=ph[2kc][0] (rows g, t=16kc+2tig..+1),
        //             a1=ph[2kc][1] (rows g+8), a2/a3 = ph[2kc+1][0/1] (t+8).
#pragma unroll
        for (int kc = 0; kc < 4; kc++) {
            unsigned a0 = ph[2 * kc][0], a1 = ph[2 * kc][1];
            unsigned a2 = ph[2 * kc + 1][0], a3 = ph[2 * kc + 1][1];
            unsigned bb[8][2];
#pragma unroll
            for (int np = 0; np < 4; np++)
                ldsm4(bb[np * 2][0], bb[np * 2][1], bb[np * 2 + 1][0], bb[np * 2 + 1][1],
                      pvb_base + bf * TWB + np * 16 * RB + kc * 32);
#pragma unroll
            for (int nt = 0; nt < 8; nt++)
                mma16(o[nt], a0, a1, a2, a3, bb[nt][0], bb[nt][1]);
            mma16(lacc, a0, a1, a2, a3, ONEH2, ONEH2);
        }
    }

    // epilogue
    float i0 = 1.f / lacc[0], i1 = 1.f / lacc[2];
    float* Op = out + (size_t)b * SEQ * EMB + h * HD;
#pragma unroll
    for (int nt = 0; nt < 8; nt++) {
        int c = nt * 8 + 2 * tig;
        *(float2*)&Op[(size_t)r0 * EMB + c] = make_float2(o[nt][0] * i0, o[nt][1] * i0);
        *(float2*)&Op[(size_t)r1 * EMB + c] = make_float2(o[nt][2] * i1, o[nt][3] * i1);
    }
}

// ---------------------------------------------------------------------------
extern "C" void kernel_launch(void* const* d_in, const int* in_sizes, int n_in,
                              void* d_out, int out_size)
{
    (void)in_sizes; (void)n_in; (void)out_size;
    const float* X  = (const float*)d_in[0];
    const float* Wq = (const float*)d_in[1];
    const float* Wk = (const float*)d_in[2];
    const float* Wv = (const float*)d_in[3];
    float* out = (float*)d_out;

    static bool attr_set = false;
    if (!attr_set) {
        cudaFuncSetAttribute(attn_mma, cudaFuncAttributeMaxDynamicSharedMemorySize, ATTN_SMEM);
        cudaFuncSetAttribute(qkv_gemm, cudaFuncAttributeMaxDynamicSharedMemorySize, QKV_SMEM);
        attr_set = true;
    }

    f2h_all<<<1024, 256>>>(X, Wq, Wk, Wv);
    qkv_gemm<<<dim3(18, MTOT / 128), 256, QKV_SMEM>>>();
    attn_mma<<<dim3(SEQ / 64, NH, BATCH), 128, ATTN_SMEM>>>(out);
}

// round 14
// speedup vs baseline: 2.9852x; 1.0008x over previous
#include <cuda_runtime.h>
#include <cuda_fp16.h>

#define BATCH 2
#define SEQ   2048
#define EMB   1024
#define NH    16
#define HD    64
#define MTOT  (BATCH * SEQ)   // 4096

// fp16 copies of inputs (converted once per launch; Wq pre-scaled by 0.125*log2e)
__device__ __half g_Xh[(size_t)MTOT * EMB];
__device__ __half g_Wqh[(size_t)EMB * EMB];
__device__ __half g_Wkh[(size_t)EMB * HD];
__device__ __half g_Wvh[(size_t)EMB * HD];
// Projected operands (fp16). Q pre-scaled (via Wq) -> S = log2-domain scores.
__device__ __half g_Q[(size_t)MTOT * EMB];
__device__ __half g_K[(size_t)MTOT * HD];
__device__ __half g_Vt[(size_t)HD * MTOT];

__device__ __forceinline__ void cp16(void* dst_smem, const void* src) {
    unsigned d = (unsigned)__cvta_generic_to_shared(dst_smem);
    asm volatile("cp.async.cg.shared.global [%0], [%1], 16;\n" :: "r"(d), "l"(src));
}

__device__ __forceinline__ float ex2(float x) {
    float y; asm("ex2.approx.ftz.f32 %0, %1;" : "=f"(y) : "f"(x)); return y;
}

__device__ __forceinline__ void mma16(float* d, unsigned a0, unsigned a1,
                                      unsigned a2, unsigned a3,
                                      unsigned b0, unsigned b1) {
    asm volatile("mma.sync.aligned.m16n8k16.row.col.f32.f16.f16.f32 "
        "{%0,%1,%2,%3},{%4,%5,%6,%7},{%8,%9},{%0,%1,%2,%3};"
        : "+f"(d[0]), "+f"(d[1]), "+f"(d[2]), "+f"(d[3])
        : "r"(a0), "r"(a1), "r"(a2), "r"(a3), "r"(b0), "r"(b1));
}

__device__ __forceinline__ void ldsm4(unsigned& r0, unsigned& r1, unsigned& r2,
                                      unsigned& r3, unsigned addr) {
    asm volatile("ldmatrix.sync.aligned.m8n8.x4.shared.b16 {%0,%1,%2,%3}, [%4];"
        : "=r"(r0), "=r"(r1), "=r"(r2), "=r"(r3) : "r"(addr));
}
__device__ __forceinline__ void ldsm4t(unsigned& r0, unsigned& r1, unsigned& r2,
                                       unsigned& r3, unsigned addr) {
    asm volatile("ldmatrix.sync.aligned.m8n8.x4.trans.shared.b16 {%0,%1,%2,%3}, [%4];"
        : "=r"(r0), "=r"(r1), "=r"(r2), "=r"(r3) : "r"(addr));
}

#define RB 144   // K/GEMM row pitch bytes (72 halves)

// ---------------------------------------------------------------------------
// Fused fp32 -> fp16 convert of all inputs (Wq scaled by 0.125*log2e).
// ---------------------------------------------------------------------------
#define N1 (MTOT * EMB / 4)
#define N2 (EMB * EMB / 4)
#define N3 (EMB * HD / 4)

__global__ __launch_bounds__(256) void f2h_all(
    const float* __restrict__ X, const float* __restrict__ Wq,
    const float* __restrict__ Wk, const float* __restrict__ Wv)
{
    const float cs = 0.125f * 1.44269504f;
    int i = blockIdx.x * blockDim.x + threadIdx.x;
    int stride = gridDim.x * blockDim.x;
    const int total = N1 + N2 + 2 * N3;
    for (; i < total; i += stride) {
        const float4* src; uint2* dst; int j; float sc = 1.f;
        if (i < N1)                { src = (const float4*)X;  dst = (uint2*)g_Xh;  j = i; }
        else if (i < N1 + N2)      { src = (const float4*)Wq; dst = (uint2*)g_Wqh; j = i - N1; sc = cs; }
        else if (i < N1 + N2 + N3) { src = (const float4*)Wk; dst = (uint2*)g_Wkh; j = i - N1 - N2; }
        else                       { src = (const float4*)Wv; dst = (uint2*)g_Wvh; j = i - N1 - N2 - N3; }
        float4 v = src[j];
        __half2 h0 = __floats2half2_rn(v.x * sc, v.y * sc);
        __half2 h1 = __floats2half2_rn(v.z * sc, v.w * sc);
        dst[j] = make_uint2(*(unsigned*)&h0, *(unsigned*)&h1);
    }
}

// ---------------------------------------------------------------------------
// Fused QKV projection GEMM, fp16 + LDSM + cp.async (unchanged from R13).
// ---------------------------------------------------------------------------
#define AW (128 * 72)
#define BW (64 * 72)
#define QKV_SMEM ((2 * AW + 2 * BW) * 2)

__global__ __launch_bounds__(256) void qkv_gemm()
{
    extern __shared__ __align__(16) __half smh[];
    __half* SA = smh;
    __half* SB = smh + 2 * AW;

    const int nb = blockIdx.x;
    const int m0 = blockIdx.y * 128;

    const __half* W; int ldw, wc0;
    if (nb < 16)      { W = g_Wqh; ldw = EMB; wc0 = nb * 64; }
    else if (nb == 16){ W = g_Wkh; ldw = HD;  wc0 = 0; }
    else              { W = g_Wvh; ldw = HD;  wc0 = 0; }

    const int tid = threadIdx.x;
    const int wid = tid >> 5, lane = tid & 31;
    const int g = lane >> 2, tig = lane & 3;
    const int wm = wid >> 1, wn = wid & 1;

    const unsigned sa_b = (unsigned)__cvta_generic_to_shared(SA);
    const unsigned sb_b = (unsigned)__cvta_generic_to_shared(SB);

    const int rowA16 = lane & 15, khA = (lane >> 4) * 8;
    const int rowT = (lane & 7) + (((lane >> 3) & 1) * 8);
    const int colT = (lane >> 4) * 8;

    const unsigned a_base = sa_b + (unsigned)((wm * 32 + rowA16) * RB + khA * 2);
    const unsigned b_base = sb_b + (unsigned)(rowT * RB + (wn * 32 + colT) * 2);

    auto issue = [&](int it) {
        const int bf = it & 1, k0 = it * 64;
#pragma unroll
        for (int l = 0; l < 4; l++) {
            int fid = tid + l * 256; int row = fid >> 3, c8 = fid & 7;
            cp16(&SA[bf * AW + row * 72 + c8 * 8],
                 g_Xh + (size_t)(m0 + row) * EMB + k0 + c8 * 8);
        }
#pragma unroll
        for (int l = 0; l < 2; l++) {
            int fid = tid + l * 256; int row = fid >> 3, c8 = fid & 7;
            cp16(&SB[bf * BW + row * 72 + c8 * 8],
                 W + (size_t)(k0 + row) * ldw + wc0 + c8 * 8);
        }
        asm volatile("cp.async.commit_group;\n");
    };

    issue(0);

    float acc[2][4][4];
#pragma unroll
    for (int mt = 0; mt < 2; mt++)
#pragma unroll
        for (int nt = 0; nt < 4; nt++)
#pragma unroll
            for (int c = 0; c < 4; c++) acc[mt][nt][c] = 0.f;

    for (int it = 0; it < 16; it++) {
        const int bf = it & 1;
        __syncthreads();
        if (it + 1 < 16) {
            issue(it + 1);
            asm volatile("cp.async.wait_group 1;\n");
        } else {
            asm volatile("cp.async.wait_group 0;\n");
        }
        __syncthreads();

        const unsigned abf = a_base + bf * AW * 2;
        const unsigned bbf = b_base + bf * BW * 2;
#pragma unroll
        for (int kc = 0; kc < 4; kc++) {
            unsigned a[2][4], bb[4][2];
#pragma unroll
            for (int mt = 0; mt < 2; mt++)
                ldsm4(a[mt][0], a[mt][1], a[mt][2], a[mt][3],
                      abf + mt * 16 * RB + kc * 32);
#pragma unroll
            for (int np = 0; np < 2; np++)
                ldsm4t(bb[np * 2][0], bb[np * 2][1], bb[np * 2 + 1][0], bb[np * 2 + 1][1],
                       bbf + kc * 16 * RB + np * 32);
#pragma unroll
            for (int mt = 0; mt < 2; mt++)
#pragma unroll
                for (int nt = 0; nt < 4; nt++)
                    mma16(acc[mt][nt], a[mt][0], a[mt][1], a[mt][2], a[mt][3],
                          bb[nt][0], bb[nt][1]);
        }
    }

#pragma unroll
    for (int mt = 0; mt < 2; mt++) {
        int r0 = m0 + wm * 32 + mt * 16 + g;
        int r1 = r0 + 8;
#pragma unroll
        for (int nt = 0; nt < 4; nt++) {
            int c = wn * 32 + nt * 8 + 2 * tig;
            __half2 h0 = __floats2half2_rn(acc[mt][nt][0], acc[mt][nt][1]);
            __half2 h1 = __floats2half2_rn(acc[mt][nt][2], acc[mt][nt][3]);
            if (nb < 16) {
                int cc = nb * 64 + c;
                *(__half2*)&g_Q[(size_t)r0 * EMB + cc] = h0;
                *(__half2*)&g_Q[(size_t)r1 * EMB + cc] = h1;
            } else if (nb == 16) {
                *(__half2*)&g_K[(size_t)r0 * HD + c] = h0;
                *(__half2*)&g_K[(size_t)r1 * HD + c] = h1;
            } else {
                g_Vt[(size_t)c       * MTOT + r0] = __low2half(h0);
                g_Vt[(size_t)(c + 1) * MTOT + r0] = __high2half(h0);
                g_Vt[(size_t)c       * MTOT + r1] = __low2half(h1);
                g_Vt[(size_t)(c + 1) * MTOT + r1] = __high2half(h1);
            }
        }
    }
}

// ---------------------------------------------------------------------------
// Flash attention: fp16 m16n8k16, P in registers, 128-token KV chunks
// (two 64-token subtiles per barrier window), cp.async double buffering.
// K buffers: [2][128 t][72h] pitch 144B. Vt buffers: [2][64 d][136h] pitch 272B.
// smem total = 2*18432 + 2*17408 = 70 KB.
// ---------------------------------------------------------------------------
#define KWH (128 * 72)    // halves per K buffer
#define VWH (64 * 136)    // halves per Vt buffer
#define KWB (KWH * 2)
#define VWB (VWH * 2)
#define VPB 272           // Vt row pitch bytes
#define ATTN_SMEM ((2 * KWH + 2 * VWH) * 2)
#define ONEH2 0x3C003C00u

__global__ __launch_bounds__(128) void attn_mma(float* __restrict__ out)
{
    extern __shared__ __align__(16) __half smem_dyn[];
    __half* SK  = smem_dyn;              // [2][128][72]
    __half* SVT = smem_dyn + 2 * KWH;    // [2][64][136]

    const int qt = gridDim.x - 1 - blockIdx.x;
    const int h  = blockIdx.y;
    const int b  = blockIdx.z;
    const int qbase = qt * 64;

    const int tid = threadIdx.x;
    const int wid = tid >> 5, lane = tid & 31;
    const int g = lane >> 2, tig = lane & 3;

    const int r0 = qbase + wid * 16 + g;
    const int r1 = r0 + 8;

    const unsigned sk_b  = (unsigned)__cvta_generic_to_shared(SK);
    const unsigned svt_b = (unsigned)__cvta_generic_to_shared(SVT);

    const int rowB = ((lane >> 4) << 3) + (lane & 7);
    const int khB  = ((lane >> 3) & 1) * 8;

    const unsigned qk_base  = sk_b  + (unsigned)(rowB * RB  + khB * 2);
    const unsigned pvb_base = svt_b + (unsigned)(rowB * VPB + khB * 2);

    // issue 128-token chunk ct into buffer ct&1
    auto issue = [&](int ct) {
        const int bf = ct & 1, kbase = ct * 128;
        const __half* Kp = g_K + (size_t)(b * SEQ + kbase) * HD;
#pragma unroll
        for (int l = 0; l < 8; l++) {           // K: 128 rows x 8 segs
            int fid = tid + l * 128; int row = fid >> 3, c8 = fid & 7;
            cp16(&SK[bf * KWH + row * 72 + c8 * 8], Kp + row * HD + c8 * 8);
        }
#pragma unroll
        for (int l = 0; l < 8; l++) {           // Vt: 64 rows x 16 segs
            int fid = tid + l * 128; int row = fid >> 4, c16 = fid & 15;
            cp16(&SVT[bf * VWH + row * 136 + c16 * 8],
                 g_Vt + (size_t)row * MTOT + b * SEQ + kbase + c16 * 8);
        }
        asm volatile("cp.async.commit_group;\n");
    };

    issue(0);

    unsigned q[4][4];
    {
        const __half* Q0 = g_Q + (size_t)(b * SEQ + r0) * EMB + h * HD;
        const __half* Q1 = g_Q + (size_t)(b * SEQ + r1) * EMB + h * HD;
#pragma unroll
        for (int kc = 0; kc < 4; kc++) {
            q[kc][0] = *(const unsigned*)(Q0 + kc * 16 + 2 * tig);
            q[kc][1] = *(const unsigned*)(Q1 + kc * 16 + 2 * tig);
            q[kc][2] = *(const unsigned*)(Q0 + kc * 16 + 2 * tig + 8);
            q[kc][3] = *(const unsigned*)(Q1 + kc * 16 + 2 * tig + 8);
        }
    }

    float o[8][4], lacc[4];
#pragma unroll
    for (int nt = 0; nt < 8; nt++)
#pragma unroll
        for (int c = 0; c < 4; c++) o[nt][c] = 0.f;
#pragma unroll
    for (int c = 0; c < 4; c++) lacc[c] = 0.f;

    // one 64-token subtile: QK -> exp -> PV, data in buffer bf, subtile st
    auto proc = [&](int bf, int st) {
        const int kbase = st * 64;
        const unsigned kbuf = qk_base  + bf * KWB + (st & 1) * 64 * RB;
        const unsigned vbuf = pvb_base + bf * VWB + (st & 1) * 128;

        float s[8][4];
#pragma unroll
        for (int nt = 0; nt < 8; nt++)
#pragma unroll
            for (int c = 0; c < 4; c++) s[nt][c] = 0.f;

#pragma unroll
        for (int kc = 0; kc < 4; kc++) {
            unsigned bb[8][2];
#pragma unroll
            for (int np = 0; np < 4; np++)
                ldsm4(bb[np * 2][0], bb[np * 2][1], bb[np * 2 + 1][0], bb[np * 2 + 1][1],
                      kbuf + np * 16 * RB + kc * 32);
#pragma unroll
            for (int nt = 0; nt < 8; nt++)
                mma16(s[nt], q[kc][0], q[kc][1], q[kc][2], q[kc][3],
                      bb[nt][0], bb[nt][1]);
        }

        unsigned ph[8][2];
        if (st == qt) {
#pragma unroll
            for (int nt = 0; nt < 8; nt++) {
                int c = kbase + nt * 8 + 2 * tig;
                float p0 = (c     <= r0) ? ex2(s[nt][0]) : 0.f;
                float p1 = (c + 1 <= r0) ? ex2(s[nt][1]) : 0.f;
                float p2 = (c     <= r1) ? ex2(s[nt][2]) : 0.f;
                float p3 = (c + 1 <= r1) ? ex2(s[nt][3]) : 0.f;
                __half2 h0 = __floats2half2_rn(p0, p1);
                __half2 h1 = __floats2half2_rn(p2, p3);
                ph[nt][0] = *(unsigned*)&h0; ph[nt][1] = *(unsigned*)&h1;
            }
        } else {
#pragma unroll
            for (int nt = 0; nt < 8; nt++) {
                __half2 h0 = __floats2half2_rn(ex2(s[nt][0]), ex2(s[nt][1]));
                __half2 h1 = __floats2half2_rn(ex2(s[nt][2]), ex2(s[nt][3]));
                ph[nt][0] = *(unsigned*)&h0; ph[nt][1] = *(unsigned*)&h1;
            }
        }

#pragma unroll
        for (int kc = 0; kc < 4; kc++) {
            unsigned a0 = ph[2 * kc][0], a1 = ph[2 * kc][1];
            unsigned a2 = ph[2 * kc + 1][0], a3 = ph[2 * kc + 1][1];
            unsigned bb[8][2];
#pragma unroll
            for (int np = 0; np < 4; np++)
                ldsm4(bb[np * 2][0], bb[np * 2][1], bb[np * 2 + 1][0], bb[np * 2 + 1][1],
                      vbuf + np * 16 * VPB + kc * 32);
#pragma unroll
            for (int nt = 0; nt < 8; nt++)
                mma16(o[nt], a0, a1, a2, a3, bb[nt][0], bb[nt][1]);
            mma16(lacc, a0, a1, a2, a3, ONEH2, ONEH2);
        }
    };

    const int nchunks = (qt + 2) >> 1;   // ceil((qt+1)/2)
    for (int ct = 0; ct < nchunks; ct++) {
        const int bf = ct & 1;
        __syncthreads();
        if (ct + 1 < nchunks) {
            issue(ct + 1);
            asm volatile("cp.async.wait_group 1;\n");
        } else {
            asm volatile("cp.async.wait_group 0;\n");
        }
        __syncthreads();

        proc(bf, 2 * ct);
        if (2 * ct + 1 <= qt) proc(bf, 2 * ct + 1);
    }

    // epilogue
    float i0 = 1.f / lacc[0], i1 = 1.f / lacc[2];
    float* Op = out + (size_t)b * SEQ * EMB + h * HD;
#pragma unroll
    for (int nt = 0; nt < 8; nt++) {
        int c = nt * 8 + 2 * tig;
        *(float2*)&Op[(size_t)r0 * EMB + c] = make_float2(o[nt][0] * i0, o[nt][1] * i0);
        *(float2*)&Op[(size_t)r1 * EMB + c] = make_float2(o[nt][2] * i1, o[nt][3] * i1);
    }
}

// ---------------------------------------------------------------------------
extern "C" void kernel_launch(void* const* d_in, const int* in_sizes, int n_in,
                              void* d_out, int out_size)
{
    (void)in_sizes; (void)n_in; (void)out_size;
    const float* X  = (const float*)d_in[0];
    const float* Wq = (const float*)d_in[1];
    const float* Wk = (const float*)d_in[2];
    const float* Wv = (const float*)d_in[3];
    float* out = (float*)d_out;

    static bool attr_set = false;
    if (!attr_set) {
        cudaFuncSetAttribute(attn_mma, cudaFuncAttributeMaxDynamicSharedMemorySize, ATTN_SMEM);
        cudaFuncSetAttribute(qkv_gemm, cudaFuncAttributeMaxDynamicSharedMemorySize, QKV_SMEM);
        attr_set = true;
    }

    f2h_all<<<1024, 256>>>(X, Wq, Wk, Wv);
    qkv_gemm<<<dim3(18, MTOT / 128), 256, QKV_SMEM>>>();
    attn_mma<<<dim3(SEQ / 64, NH, BATCH), 128, ATTN_SMEM>>>(out);
}

// round 15
// speedup vs baseline: 3.0070x; 1.0073x over previous
#include <cuda_runtime.h>
#include <cuda_fp16.h>

#define BATCH 2
#define SEQ   2048
#define EMB   1024
#define NH    16
#define HD    64
#define MTOT  (BATCH * SEQ)   // 4096

// fp16 copies of inputs (converted once per launch; Wq pre-scaled by 0.125*log2e)
__device__ __half g_Xh[(size_t)MTOT * EMB];
__device__ __half g_Wqh[(size_t)EMB * EMB];
__device__ __half g_Wkh[(size_t)EMB * HD];
__device__ __half g_Wvh[(size_t)EMB * HD];
// Projected operands (fp16). Q pre-scaled (via Wq) -> S = log2-domain scores.
__device__ __half g_Q[(size_t)MTOT * EMB];
__device__ __half g_K[(size_t)MTOT * HD];
__device__ __half g_Vt[(size_t)HD * MTOT];

__device__ __forceinline__ void cp16(void* dst_smem, const void* src) {
    unsigned d = (unsigned)__cvta_generic_to_shared(dst_smem);
    asm volatile("cp.async.cg.shared.global [%0], [%1], 16;\n" :: "r"(d), "l"(src));
}

__device__ __forceinline__ float ex2(float x) {
    float y; asm("ex2.approx.ftz.f32 %0, %1;" : "=f"(y) : "f"(x)); return y;
}

__device__ __forceinline__ void mma16(float* d, unsigned a0, unsigned a1,
                                      unsigned a2, unsigned a3,
                                      unsigned b0, unsigned b1) {
    asm volatile("mma.sync.aligned.m16n8k16.row.col.f32.f16.f16.f32 "
        "{%0,%1,%2,%3},{%4,%5,%6,%7},{%8,%9},{%0,%1,%2,%3};"
        : "+f"(d[0]), "+f"(d[1]), "+f"(d[2]), "+f"(d[3])
        : "r"(a0), "r"(a1), "r"(a2), "r"(a3), "r"(b0), "r"(b1));
}

__device__ __forceinline__ void ldsm4(unsigned& r0, unsigned& r1, unsigned& r2,
                                      unsigned& r3, unsigned addr) {
    asm volatile("ldmatrix.sync.aligned.m8n8.x4.shared.b16 {%0,%1,%2,%3}, [%4];"
        : "=r"(r0), "=r"(r1), "=r"(r2), "=r"(r3) : "r"(addr));
}
__device__ __forceinline__ void ldsm4t(unsigned& r0, unsigned& r1, unsigned& r2,
                                       unsigned& r3, unsigned addr) {
    asm volatile("ldmatrix.sync.aligned.m8n8.x4.trans.shared.b16 {%0,%1,%2,%3}, [%4];"
        : "=r"(r0), "=r"(r1), "=r"(r2), "=r"(r3) : "r"(addr));
}

#define RB 144   // K/GEMM row pitch bytes (72 halves)

// ---------------------------------------------------------------------------
// Fused fp32 -> fp16 convert of all inputs (Wq scaled by 0.125*log2e).
// ---------------------------------------------------------------------------
#define N1 (MTOT * EMB / 4)
#define N2 (EMB * EMB / 4)
#define N3 (EMB * HD / 4)

__global__ __launch_bounds__(256) void f2h_all(
    const float* __restrict__ X, const float* __restrict__ Wq,
    const float* __restrict__ Wk, const float* __restrict__ Wv)
{
    const float cs = 0.125f * 1.44269504f;
    int i = blockIdx.x * blockDim.x + threadIdx.x;
    int stride = gridDim.x * blockDim.x;
    const int total = N1 + N2 + 2 * N3;
    for (; i < total; i += stride) {
        const float4* src; uint2* dst; int j; float sc = 1.f;
        if (i < N1)                { src = (const float4*)X;  dst = (uint2*)g_Xh;  j = i; }
        else if (i < N1 + N2)      { src = (const float4*)Wq; dst = (uint2*)g_Wqh; j = i - N1; sc = cs; }
        else if (i < N1 + N2 + N3) { src = (const float4*)Wk; dst = (uint2*)g_Wkh; j = i - N1 - N2; }
        else                       { src = (const float4*)Wv; dst = (uint2*)g_Wvh; j = i - N1 - N2 - N3; }
        float4 v = src[j];
        __half2 h0 = __floats2half2_rn(v.x * sc, v.y * sc);
        __half2 h1 = __floats2half2_rn(v.z * sc, v.w * sc);
        dst[j] = make_uint2(*(unsigned*)&h0, *(unsigned*)&h1);
    }
}

// ---------------------------------------------------------------------------
// Fused QKV projection GEMM, fp16 + LDSM + cp.async (unchanged from R13).
// ---------------------------------------------------------------------------
#define AW (128 * 72)
#define BW (64 * 72)
#define QKV_SMEM ((2 * AW + 2 * BW) * 2)

__global__ __launch_bounds__(256) void qkv_gemm()
{
    extern __shared__ __align__(16) __half smh[];
    __half* SA = smh;
    __half* SB = smh + 2 * AW;

    const int nb = blockIdx.x;
    const int m0 = blockIdx.y * 128;

    const __half* W; int ldw, wc0;
    if (nb < 16)      { W = g_Wqh; ldw = EMB; wc0 = nb * 64; }
    else if (nb == 16){ W = g_Wkh; ldw = HD;  wc0 = 0; }
    else              { W = g_Wvh; ldw = HD;  wc0 = 0; }

    const int tid = threadIdx.x;
    const int wid = tid >> 5, lane = tid & 31;
    const int g = lane >> 2, tig = lane & 3;
    const int wm = wid >> 1, wn = wid & 1;

    const unsigned sa_b = (unsigned)__cvta_generic_to_shared(SA);
    const unsigned sb_b = (unsigned)__cvta_generic_to_shared(SB);

    const int rowA16 = lane & 15, khA = (lane >> 4) * 8;
    const int rowT = (lane & 7) + (((lane >> 3) & 1) * 8);
    const int colT = (lane >> 4) * 8;

    const unsigned a_base = sa_b + (unsigned)((wm * 32 + rowA16) * RB + khA * 2);
    const unsigned b_base = sb_b + (unsigned)(rowT * RB + (wn * 32 + colT) * 2);

    auto issue = [&](int it) {
        const int bf = it & 1, k0 = it * 64;
#pragma unroll
        for (int l = 0; l < 4; l++) {
            int fid = tid + l * 256; int row = fid >> 3, c8 = fid & 7;
            cp16(&SA[bf * AW + row * 72 + c8 * 8],
                 g_Xh + (size_t)(m0 + row) * EMB + k0 + c8 * 8);
        }
#pragma unroll
        for (int l = 0; l < 2; l++) {
            int fid = tid + l * 256; int row = fid >> 3, c8 = fid & 7;
            cp16(&SB[bf * BW + row * 72 + c8 * 8],
                 W + (size_t)(k0 + row) * ldw + wc0 + c8 * 8);
        }
        asm volatile("cp.async.commit_group;\n");
    };

    issue(0);

    float acc[2][4][4];
#pragma unroll
    for (int mt = 0; mt < 2; mt++)
#pragma unroll
        for (int nt = 0; nt < 4; nt++)
#pragma unroll
            for (int c = 0; c < 4; c++) acc[mt][nt][c] = 0.f;

    for (int it = 0; it < 16; it++) {
        const int bf = it & 1;
        __syncthreads();
        if (it + 1 < 16) {
            issue(it + 1);
            asm volatile("cp.async.wait_group 1;\n");
        } else {
            asm volatile("cp.async.wait_group 0;\n");
        }
        __syncthreads();

        const unsigned abf = a_base + bf * AW * 2;
        const unsigned bbf = b_base + bf * BW * 2;
#pragma unroll
        for (int kc = 0; kc < 4; kc++) {
            unsigned a[2][4], bb[4][2];
#pragma unroll
            for (int mt = 0; mt < 2; mt++)
                ldsm4(a[mt][0], a[mt][1], a[mt][2], a[mt][3],
                      abf + mt * 16 * RB + kc * 32);
#pragma unroll
            for (int np = 0; np < 2; np++)
                ldsm4t(bb[np * 2][0], bb[np * 2][1], bb[np * 2 + 1][0], bb[np * 2 + 1][1],
                       bbf + kc * 16 * RB + np * 32);
#pragma unroll
            for (int mt = 0; mt < 2; mt++)
#pragma unroll
                for (int nt = 0; nt < 4; nt++)
                    mma16(acc[mt][nt], a[mt][0], a[mt][1], a[mt][2], a[mt][3],
                          bb[nt][0], bb[nt][1]);
        }
    }

#pragma unroll
    for (int mt = 0; mt < 2; mt++) {
        int r0 = m0 + wm * 32 + mt * 16 + g;
        int r1 = r0 + 8;
#pragma unroll
        for (int nt = 0; nt < 4; nt++) {
            int c = wn * 32 + nt * 8 + 2 * tig;
            __half2 h0 = __floats2half2_rn(acc[mt][nt][0], acc[mt][nt][1]);
            __half2 h1 = __floats2half2_rn(acc[mt][nt][2], acc[mt][nt][3]);
            if (nb < 16) {
                int cc = nb * 64 + c;
                *(__half2*)&g_Q[(size_t)r0 * EMB + cc] = h0;
                *(__half2*)&g_Q[(size_t)r1 * EMB + cc] = h1;
            } else if (nb == 16) {
                *(__half2*)&g_K[(size_t)r0 * HD + c] = h0;
                *(__half2*)&g_K[(size_t)r1 * HD + c] = h1;
            } else {
                g_Vt[(size_t)c       * MTOT + r0] = __low2half(h0);
                g_Vt[(size_t)(c + 1) * MTOT + r0] = __high2half(h0);
                g_Vt[(size_t)c       * MTOT + r1] = __low2half(h1);
                g_Vt[(size_t)(c + 1) * MTOT + r1] = __high2half(h1);
            }
        }
    }
}

// ---------------------------------------------------------------------------
// Flash attention: fp16 m16n8k16, P in registers, 128-token KV chunks
// (two 64-token subtiles per barrier window), cp.async double buffering.
// K buffers: [2][128 t][72h] pitch 144B. Vt buffers: [2][64 d][136h] pitch 272B.
// smem total = 2*18432 + 2*17408 = 70 KB.
// ---------------------------------------------------------------------------
#define KWH (128 * 72)    // halves per K buffer
#define VWH (64 * 136)    // halves per Vt buffer
#define KWB (KWH * 2)
#define VWB (VWH * 2)
#define VPB 272           // Vt row pitch bytes
#define ATTN_SMEM ((2 * KWH + 2 * VWH) * 2)
#define ONEH2 0x3C003C00u

__global__ __launch_bounds__(128) void attn_mma(float* __restrict__ out)
{
    extern __shared__ __align__(16) __half smem_dyn[];
    __half* SK  = smem_dyn;              // [2][128][72]
    __half* SVT = smem_dyn + 2 * KWH;    // [2][64][136]

    const int qt = gridDim.x - 1 - blockIdx.x;
    const int h  = blockIdx.y;
    const int b  = blockIdx.z;
    const int qbase = qt * 64;

    const int tid = threadIdx.x;
    const int wid = tid >> 5, lane = tid & 31;
    const int g = lane >> 2, tig = lane & 3;

    const int r0 = qbase + wid * 16 + g;
    const int r1 = r0 + 8;

    const unsigned sk_b  = (unsigned)__cvta_generic_to_shared(SK);
    const unsigned svt_b = (unsigned)__cvta_generic_to_shared(SVT);

    const int rowB = ((lane >> 4) << 3) + (lane & 7);
    const int khB  = ((lane >> 3) & 1) * 8;

    const unsigned qk_base  = sk_b  + (unsigned)(rowB * RB  + khB * 2);
    const unsigned pvb_base = svt_b + (unsigned)(rowB * VPB + khB * 2);

    // issue 128-token chunk ct into buffer ct&1
    auto issue = [&](int ct) {
        const int bf = ct & 1, kbase = ct * 128;
        const __half* Kp = g_K + (size_t)(b * SEQ + kbase) * HD;
#pragma unroll
        for (int l = 0; l < 8; l++) {           // K: 128 rows x 8 segs
            int fid = tid + l * 128; int row = fid >> 3, c8 = fid & 7;
            cp16(&SK[bf * KWH + row * 72 + c8 * 8], Kp + row * HD + c8 * 8);
        }
#pragma unroll
        for (int l = 0; l < 8; l++) {           // Vt: 64 rows x 16 segs
            int fid = tid + l * 128; int row = fid >> 4, c16 = fid & 15;
            cp16(&SVT[bf * VWH + row * 136 + c16 * 8],
                 g_Vt + (size_t)row * MTOT + b * SEQ + kbase + c16 * 8);
        }
        asm volatile("cp.async.commit_group;\n");
    };

    issue(0);

    unsigned q[4][4];
    {
        const __half* Q0 = g_Q + (size_t)(b * SEQ + r0) * EMB + h * HD;
        const __half* Q1 = g_Q + (size_t)(b * SEQ + r1) * EMB + h * HD;
#pragma unroll
        for (int kc = 0; kc < 4; kc++) {
            q[kc][0] = *(const unsigned*)(Q0 + kc * 16 + 2 * tig);
            q[kc][1] = *(const unsigned*)(Q1 + kc * 16 + 2 * tig);
            q[kc][2] = *(const unsigned*)(Q0 + kc * 16 + 2 * tig + 8);
            q[kc][3] = *(const unsigned*)(Q1 + kc * 16 + 2 * tig + 8);
        }
    }

    float o[8][4], lacc[4];
#pragma unroll
    for (int nt = 0; nt < 8; nt++)
#pragma unroll
        for (int c = 0; c < 4; c++) o[nt][c] = 0.f;
#pragma unroll
    for (int c = 0; c < 4; c++) lacc[c] = 0.f;

    // one 64-token subtile: QK -> exp -> PV, data in buffer bf, subtile st
    auto proc = [&](int bf, int st) {
        const int kbase = st * 64;
        const unsigned kbuf = qk_base  + bf * KWB + (st & 1) * 64 * RB;
        const unsigned vbuf = pvb_base + bf * VWB + (st & 1) * 128;

        float s[8][4];
#pragma unroll
        for (int nt = 0; nt < 8; nt++)
#pragma unroll
            for (int c = 0; c < 4; c++) s[nt][c] = 0.f;

#pragma unroll
        for (int kc = 0; kc < 4; kc++) {
            unsigned bb[8][2];
#pragma unroll
            for (int np = 0; np < 4; np++)
                ldsm4(bb[np * 2][0], bb[np * 2][1], bb[np * 2 + 1][0], bb[np * 2 + 1][1],
                      kbuf + np * 16 * RB + kc * 32);
#pragma unroll
            for (int nt = 0; nt < 8; nt++)
                mma16(s[nt], q[kc][0], q[kc][1], q[kc][2], q[kc][3],
                      bb[nt][0], bb[nt][1]);
        }

        unsigned ph[8][2];
        if (st == qt) {
#pragma unroll
            for (int nt = 0; nt < 8; nt++) {
                int c = kbase + nt * 8 + 2 * tig;
                float p0 = (c     <= r0) ? ex2(s[nt][0]) : 0.f;
                float p1 = (c + 1 <= r0) ? ex2(s[nt][1]) : 0.f;
                float p2 = (c     <= r1) ? ex2(s[nt][2]) : 0.f;
                float p3 = (c + 1 <= r1) ? ex2(s[nt][3]) : 0.f;
                __half2 h0 = __floats2half2_rn(p0, p1);
                __half2 h1 = __floats2half2_rn(p2, p3);
                ph[nt][0] = *(unsigned*)&h0; ph[nt][1] = *(unsigned*)&h1;
            }
        } else {
#pragma unroll
            for (int nt = 0; nt < 8; nt++) {
                __half2 h0 = __floats2half2_rn(ex2(s[nt][0]), ex2(s[nt][1]));
                __half2 h1 = __floats2half2_rn(ex2(s[nt][2]), ex2(s[nt][3]));
                ph[nt][0] = *(unsigned*)&h0; ph[nt][1] = *(unsigned*)&h1;
            }
        }

#pragma unroll
        for (int kc = 0; kc < 4; kc++) {
            unsigned a0 = ph[2 * kc][0], a1 = ph[2 * kc][1];
            unsigned a2 = ph[2 * kc + 1][0], a3 = ph[2 * kc + 1][1];
            unsigned bb[8][2];
#pragma unroll
            for (int np = 0; np < 4; np++)
                ldsm4(bb[np * 2][0], bb[np * 2][1], bb[np * 2 + 1][0], bb[np * 2 + 1][1],
                      vbuf + np * 16 * VPB + kc * 32);
#pragma unroll
            for (int nt = 0; nt < 8; nt++)
                mma16(o[nt], a0, a1, a2, a3, bb[nt][0], bb[nt][1]);
            mma16(lacc, a0, a1, a2, a3, ONEH2, ONEH2);
        }
    };

    const int nchunks = (qt + 2) >> 1;   // ceil((qt+1)/2)
    for (int ct = 0; ct < nchunks; ct++) {
        const int bf = ct & 1;
        __syncthreads();
        if (ct + 1 < nchunks) {
            issue(ct + 1);
            asm volatile("cp.async.wait_group 1;\n");
        } else {
            asm volatile("cp.async.wait_group 0;\n");
        }
        __syncthreads();

        proc(bf, 2 * ct);
        if (2 * ct + 1 <= qt) proc(bf, 2 * ct + 1);
    }

    // epilogue
    float i0 = 1.f / lacc[0], i1 = 1.f / lacc[2];
    float* Op = out + (size_t)b * SEQ * EMB + h * HD;
#pragma unroll
    for (int nt = 0; nt < 8; nt++) {
        int c = nt * 8 + 2 * tig;
        *(float2*)&Op[(size_t)r0 * EMB + c] = make_float2(o[nt][0] * i0, o[nt][1] * i0);
        *(float2*)&Op[(size_t)r1 * EMB + c] = make_float2(o[nt][2] * i1, o[nt][3] * i1);
    }
}

// ---------------------------------------------------------------------------
extern "C" void kernel_launch(void* const* d_in, const int* in_sizes, int n_in,
                              void* d_out, int out_size)
{
    (void)in_sizes; (void)n_in; (void)out_size;
    const float* X  = (const float*)d_in[0];
    const float* Wq = (const float*)d_in[1];
    const float* Wk = (const float*)d_in[2];
    const float* Wv = (const float*)d_in[3];
    float* out = (float*)d_out;

    static bool attr_set = false;
    if (!attr_set) {
        cudaFuncSetAttribute(attn_mma, cudaFuncAttributeMaxDynamicSharedMemorySize, ATTN_SMEM);
        cudaFuncSetAttribute(qkv_gemm, cudaFuncAttributeMaxDynamicSharedMemorySize, QKV_SMEM);
        attr_set = true;
    }

    f2h_all<<<1024, 256>>>(X, Wq, Wk, Wv);
    qkv_gemm<<<dim3(18, MTOT / 128), 256, QKV_SMEM>>>();
    attn_mma<<<dim3(SEQ / 64, NH, BATCH), 128, ATTN_SMEM>>>(out);
}

// round 16
// speedup vs baseline: 3.1633x; 1.0520x over previous
#include <cuda_runtime.h>
#include <cuda_fp16.h>

#define BATCH 2
#define SEQ   2048
#define EMB   1024
#define NH    16
#define HD    64
#define MTOT  (BATCH * SEQ)   // 4096

// fp16 copies of inputs (converted once per launch; Wq pre-scaled by 0.125*log2e)
__device__ __half g_Xh[(size_t)MTOT * EMB];
__device__ __half g_Wqh[(size_t)EMB * EMB];
__device__ __half g_Wkh[(size_t)EMB * HD];
__device__ __half g_Wvh[(size_t)EMB * HD];
// Projected operands (fp16). Q pre-scaled (via Wq) -> S = log2-domain scores.
__device__ __half g_Q[(size_t)MTOT * EMB];
__device__ __half g_K[(size_t)MTOT * HD];
__device__ __half g_Vt[(size_t)HD * MTOT];

__device__ __forceinline__ void cp16(void* dst_smem, const void* src) {
    unsigned d = (unsigned)__cvta_generic_to_shared(dst_smem);
    asm volatile("cp.async.cg.shared.global [%0], [%1], 16;\n" :: "r"(d), "l"(src));
}

__device__ __forceinline__ float ex2(float x) {
    float y; asm("ex2.approx.ftz.f32 %0, %1;" : "=f"(y) : "f"(x)); return y;
}

__device__ __forceinline__ void mma16(float* d, unsigned a0, unsigned a1,
                                      unsigned a2, unsigned a3,
                                      unsigned b0, unsigned b1) {
    asm volatile("mma.sync.aligned.m16n8k16.row.col.f32.f16.f16.f32 "
        "{%0,%1,%2,%3},{%4,%5,%6,%7},{%8,%9},{%0,%1,%2,%3};"
        : "+f"(d[0]), "+f"(d[1]), "+f"(d[2]), "+f"(d[3])
        : "r"(a0), "r"(a1), "r"(a2), "r"(a3), "r"(b0), "r"(b1));
}

__device__ __forceinline__ void ldsm4(unsigned& r0, unsigned& r1, unsigned& r2,
                                      unsigned& r3, unsigned addr) {
    asm volatile("ldmatrix.sync.aligned.m8n8.x4.shared.b16 {%0,%1,%2,%3}, [%4];"
        : "=r"(r0), "=r"(r1), "=r"(r2), "=r"(r3) : "r"(addr));
}
__device__ __forceinline__ void ldsm4t(unsigned& r0, unsigned& r1, unsigned& r2,
                                       unsigned& r3, unsigned addr) {
    asm volatile("ldmatrix.sync.aligned.m8n8.x4.trans.shared.b16 {%0,%1,%2,%3}, [%4];"
        : "=r"(r0), "=r"(r1), "=r"(r2), "=r"(r3) : "r"(addr));
}

#define RB 144   // A/K row pitch bytes (72 halves)

// ---------------------------------------------------------------------------
// Fused fp32 -> fp16 convert of all inputs (Wq scaled by 0.125*log2e).
// ---------------------------------------------------------------------------
#define N1 (MTOT * EMB / 4)
#define N2 (EMB * EMB / 4)
#define N3 (EMB * HD / 4)

__global__ __launch_bounds__(256) void f2h_all(
    const float* __restrict__ X, const float* __restrict__ Wq,
    const float* __restrict__ Wk, const float* __restrict__ Wv)
{
    const float cs = 0.125f * 1.44269504f;
    int i = blockIdx.x * blockDim.x + threadIdx.x;
    int stride = gridDim.x * blockDim.x;
    const int total = N1 + N2 + 2 * N3;
    for (; i < total; i += stride) {
        const float4* src; uint2* dst; int j; float sc = 1.f;
        if (i < N1)                { src = (const float4*)X;  dst = (uint2*)g_Xh;  j = i; }
        else if (i < N1 + N2)      { src = (const float4*)Wq; dst = (uint2*)g_Wqh; j = i - N1; sc = cs; }
        else if (i < N1 + N2 + N3) { src = (const float4*)Wk; dst = (uint2*)g_Wkh; j = i - N1 - N2; }
        else                       { src = (const float4*)Wv; dst = (uint2*)g_Wvh; j = i - N1 - N2 - N3; }
        float4 v = src[j];
        __half2 h0 = __floats2half2_rn(v.x * sc, v.y * sc);
        __half2 h1 = __floats2half2_rn(v.z * sc, v.w * sc);
        dst[j] = make_uint2(*(unsigned*)&h0, *(unsigned*)&h1);
    }
}

// ---------------------------------------------------------------------------
// Fused QKV projection GEMM, BM=128 BN=128 BK=64, fp16 + LDSM + cp.async.
// blockIdx.x: 0..7 -> Q 128-col blocks; 8 -> [K|V] fused block
// (B cols 0-63 = Wk, 64-127 = Wv). Warp tile 32x64 (8 warps: 4m x 2n).
// ---------------------------------------------------------------------------
#define AW (128 * 72)     // halves per A buffer (pitch 144B)
#define BPB 272           // B row pitch bytes (136 halves)
#define BW (64 * 136)     // halves per B buffer
#define QKV_SMEM ((2 * AW + 2 * BW) * 2)   // ~70 KB

__global__ __launch_bounds__(256) void qkv_gemm()
{
    extern __shared__ __align__(16) __half smh[];
    __half* SA = smh;                 // [2][128][72]
    __half* SB = smh + 2 * AW;        // [2][64][136]

    const int nb = blockIdx.x;        // 0..7 Q, 8 = K|V
    const int m0 = blockIdx.y * 128;
    const bool isQ = (nb < 8);

    const int tid = threadIdx.x;
    const int wid = tid >> 5, lane = tid & 31;
    const int g = lane >> 2, tig = lane & 3;
    const int wm = wid >> 1, wn = wid & 1;

    const unsigned sa_b = (unsigned)__cvta_generic_to_shared(SA);
    const unsigned sb_b = (unsigned)__cvta_generic_to_shared(SB);

    const int rowA16 = lane & 15, khA = (lane >> 4) * 8;
    const int rowT = (lane & 7) + (((lane >> 3) & 1) * 8);
    const int colT = (lane >> 4) * 8;

    const unsigned a_base = sa_b + (unsigned)((wm * 32 + rowA16) * RB + khA * 2);
    const unsigned b_base = sb_b + (unsigned)(rowT * BPB + (wn * 64 + colT) * 2);

    auto issue = [&](int it) {
        const int bf = it & 1, k0 = it * 64;
        // A tile 128x64 halves: 1024 x 16B, 4 per thread
#pragma unroll
        for (int l = 0; l < 4; l++) {
            int fid = tid + l * 256; int row = fid >> 3, c8 = fid & 7;
            cp16(&SA[bf * AW + row * 72 + c8 * 8],
                 g_Xh + (size_t)(m0 + row) * EMB + k0 + c8 * 8);
        }
        // B tile 64x128 halves: 1024 x 16B, 4 per thread
#pragma unroll
        for (int l = 0; l < 4; l++) {
            int fid = tid + l * 256; int row = fid >> 4, c8 = fid & 15;
            const __half* src;
            if (isQ)            src = g_Wqh + (size_t)(k0 + row) * EMB + nb * 128 + c8 * 8;
            else if (c8 < 8)    src = g_Wkh + (size_t)(k0 + row) * HD + c8 * 8;
            else                src = g_Wvh + (size_t)(k0 + row) * HD + (c8 - 8) * 8;
            cp16(&SB[bf * BW + row * 136 + c8 * 8], src);
        }
        asm volatile("cp.async.commit_group;\n");
    };

    issue(0);

    float acc[2][8][4];
#pragma unroll
    for (int mt = 0; mt < 2; mt++)
#pragma unroll
        for (int nt = 0; nt < 8; nt++)
#pragma unroll
            for (int c = 0; c < 4; c++) acc[mt][nt][c] = 0.f;

    for (int it = 0; it < 16; it++) {
        const int bf = it & 1;
        __syncthreads();
        if (it + 1 < 16) {
            issue(it + 1);
            asm volatile("cp.async.wait_group 1;\n");
        } else {
            asm volatile("cp.async.wait_group 0;\n");
        }
        __syncthreads();

        const unsigned abf = a_base + bf * AW * 2;
        const unsigned bbf = b_base + bf * BW * 2;
#pragma unroll
        for (int kc = 0; kc < 4; kc++) {
            unsigned a[2][4], bb[8][2];
#pragma unroll
            for (int mt = 0; mt < 2; mt++)
                ldsm4(a[mt][0], a[mt][1], a[mt][2], a[mt][3],
                      abf + mt * 16 * RB + kc * 32);
#pragma unroll
            for (int np = 0; np < 4; np++)
                ldsm4t(bb[np * 2][0], bb[np * 2][1], bb[np * 2 + 1][0], bb[np * 2 + 1][1],
                       bbf + kc * 16 * BPB + np * 32);
#pragma unroll
            for (int mt = 0; mt < 2; mt++)
#pragma unroll
                for (int nt = 0; nt < 8; nt++)
                    mma16(acc[mt][nt], a[mt][0], a[mt][1], a[mt][2], a[mt][3],
                          bb[nt][0], bb[nt][1]);
        }
    }

#pragma unroll
    for (int mt = 0; mt < 2; mt++) {
        int r0 = m0 + wm * 32 + mt * 16 + g;
        int r1 = r0 + 8;
#pragma unroll
        for (int nt = 0; nt < 8; nt++) {
            int c = nt * 8 + 2 * tig;      // column within this warp's 64-wide slab
            __half2 h0 = __floats2half2_rn(acc[mt][nt][0], acc[mt][nt][1]);
            __half2 h1 = __floats2half2_rn(acc[mt][nt][2], acc[mt][nt][3]);
            if (isQ) {
                int cc = nb * 128 + wn * 64 + c;
                *(__half2*)&g_Q[(size_t)r0 * EMB + cc] = h0;
                *(__half2*)&g_Q[(size_t)r1 * EMB + cc] = h1;
            } else if (wn == 0) {
                // K columns 0-63
                *(__half2*)&g_K[(size_t)r0 * HD + c] = h0;
                *(__half2*)&g_K[(size_t)r1 * HD + c] = h1;
            } else {
                // V columns -> g_Vt transposed
                g_Vt[(size_t)c       * MTOT + r0] = __low2half(h0);
                g_Vt[(size_t)(c + 1) * MTOT + r0] = __high2half(h0);
                g_Vt[(size_t)c       * MTOT + r1] = __low2half(h1);
                g_Vt[(size_t)(c + 1) * MTOT + r1] = __high2half(h1);
            }
        }
    }
}

// ---------------------------------------------------------------------------
// Flash attention (unchanged from R15): fp16 m16n8k16, P in registers,
// 128-token KV chunks, cp.async double buffering.
// ---------------------------------------------------------------------------
#define KWH (128 * 72)
#define VWH (64 * 136)
#define KWB (KWH * 2)
#define VWB (VWH * 2)
#define VPB 272
#define ATTN_SMEM ((2 * KWH + 2 * VWH) * 2)
#define ONEH2 0x3C003C00u

__global__ __launch_bounds__(128) void attn_mma(float* __restrict__ out)
{
    extern __shared__ __align__(16) __half smem_dyn[];
    __half* SK  = smem_dyn;
    __half* SVT = smem_dyn + 2 * KWH;

    const int qt = gridDim.x - 1 - blockIdx.x;
    const int h  = blockIdx.y;
    const int b  = blockIdx.z;
    const int qbase = qt * 64;

    const int tid = threadIdx.x;
    const int wid = tid >> 5, lane = tid & 31;
    const int g = lane >> 2, tig = lane & 3;

    const int r0 = qbase + wid * 16 + g;
    const int r1 = r0 + 8;

    const unsigned sk_b  = (unsigned)__cvta_generic_to_shared(SK);
    const unsigned svt_b = (unsigned)__cvta_generic_to_shared(SVT);

    const int rowB = ((lane >> 4) << 3) + (lane & 7);
    const int khB  = ((lane >> 3) & 1) * 8;

    const unsigned qk_base  = sk_b  + (unsigned)(rowB * RB  + khB * 2);
    const unsigned pvb_base = svt_b + (unsigned)(rowB * VPB + khB * 2);

    auto issue = [&](int ct) {
        const int bf = ct & 1, kbase = ct * 128;
        const __half* Kp = g_K + (size_t)(b * SEQ + kbase) * HD;
#pragma unroll
        for (int l = 0; l < 8; l++) {
            int fid = tid + l * 128; int row = fid >> 3, c8 = fid & 7;
            cp16(&SK[bf * KWH + row * 72 + c8 * 8], Kp + row * HD + c8 * 8);
        }
#pragma unroll
        for (int l = 0; l < 8; l++) {
            int fid = tid + l * 128; int row = fid >> 4, c16 = fid & 15;
            cp16(&SVT[bf * VWH + row * 136 + c16 * 8],
                 g_Vt + (size_t)row * MTOT + b * SEQ + kbase + c16 * 8);
        }
        asm volatile("cp.async.commit_group;\n");
    };

    issue(0);

    unsigned q[4][4];
    {
        const __half* Q0 = g_Q + (size_t)(b * SEQ + r0) * EMB + h * HD;
        const __half* Q1 = g_Q + (size_t)(b * SEQ + r1) * EMB + h * HD;
#pragma unroll
        for (int kc = 0; kc < 4; kc++) {
            q[kc][0] = *(const unsigned*)(Q0 + kc * 16 + 2 * tig);
            q[kc][1] = *(const unsigned*)(Q1 + kc * 16 + 2 * tig);
            q[kc][2] = *(const unsigned*)(Q0 + kc * 16 + 2 * tig + 8);
            q[kc][3] = *(const unsigned*)(Q1 + kc * 16 + 2 * tig + 8);
        }
    }

    float o[8][4], lacc[4];
#pragma unroll
    for (int nt = 0; nt < 8; nt++)
#pragma unroll
        for (int c = 0; c < 4; c++) o[nt][c] = 0.f;
#pragma unroll
    for (int c = 0; c < 4; c++) lacc[c] = 0.f;

    auto proc = [&](int bf, int st) {
        const int kbase = st * 64;
        const unsigned kbuf = qk_base  + bf * KWB + (st & 1) * 64 * RB;
        const unsigned vbuf = pvb_base + bf * VWB + (st & 1) * 128;

        float s[8][4];
#pragma unroll
        for (int nt = 0; nt < 8; nt++)
#pragma unroll
            for (int c = 0; c < 4; c++) s[nt][c] = 0.f;

#pragma unroll
        for (int kc = 0; kc < 4; kc++) {
            unsigned bb[8][2];
#pragma unroll
            for (int np = 0; np < 4; np++)
                ldsm4(bb[np * 2][0], bb[np * 2][1], bb[np * 2 + 1][0], bb[np * 2 + 1][1],
                      kbuf + np * 16 * RB + kc * 32);
#pragma unroll
            for (int nt = 0; nt < 8; nt++)
                mma16(s[nt], q[kc][0], q[kc][1], q[kc][2], q[kc][3],
                      bb[nt][0], bb[nt][1]);
        }

        unsigned ph[8][2];
        if (st == qt) {
#pragma unroll
            for (int nt = 0; nt < 8; nt++) {
                int c = kbase + nt * 8 + 2 * tig;
                float p0 = (c     <= r0) ? ex2(s[nt][0]) : 0.f;
                float p1 = (c + 1 <= r0) ? ex2(s[nt][1]) : 0.f;
                float p2 = (c     <= r1) ? ex2(s[nt][2]) : 0.f;
                float p3 = (c + 1 <= r1) ? ex2(s[nt][3]) : 0.f;
                __half2 h0 = __floats2half2_rn(p0, p1);
                __half2 h1 = __floats2half2_rn(p2, p3);
                ph[nt][0] = *(unsigned*)&h0; ph[nt][1] = *(unsigned*)&h1;
            }
        } else {
#pragma unroll
            for (int nt = 0; nt < 8; nt++) {
                __half2 h0 = __floats2half2_rn(ex2(s[nt][0]), ex2(s[nt][1]));
                __half2 h1 = __floats2half2_rn(ex2(s[nt][2]), ex2(s[nt][3]));
                ph[nt][0] = *(unsigned*)&h0; ph[nt][1] = *(unsigned*)&h1;
            }
        }

#pragma unroll
        for (int kc = 0; kc < 4; kc++) {
            unsigned a0 = ph[2 * kc][0], a1 = ph[2 * kc][1];
            unsigned a2 = ph[2 * kc + 1][0], a3 = ph[2 * kc + 1][1];
            unsigned bb[8][2];
#pragma unroll
            for (int np = 0; np < 4; np++)
                ldsm4(bb[np * 2][0], bb[np * 2][1], bb[np * 2 + 1][0], bb[np * 2 + 1][1],
                      vbuf + np * 16 * VPB + kc * 32);
#pragma unroll
            for (int nt = 0; nt < 8; nt++)
                mma16(o[nt], a0, a1, a2, a3, bb[nt][0], bb[nt][1]);
            mma16(lacc, a0, a1, a2, a3, ONEH2, ONEH2);
        }
    };

    const int nchunks = (qt + 2) >> 1;
    for (int ct = 0; ct < nchunks; ct++) {
        const int bf = ct & 1;
        __syncthreads();
        if (ct + 1 < nchunks) {
            issue(ct + 1);
            asm volatile("cp.async.wait_group 1;\n");
        } else {
            asm volatile("cp.async.wait_group 0;\n");
        }
        __syncthreads();

        proc(bf, 2 * ct);
        if (2 * ct + 1 <= qt) proc(bf, 2 * ct + 1);
    }

    float i0 = 1.f / lacc[0], i1 = 1.f / lacc[2];
    float* Op = out + (size_t)b * SEQ * EMB + h * HD;
#pragma unroll
    for (int nt = 0; nt < 8; nt++) {
        int c = nt * 8 + 2 * tig;
        *(float2*)&Op[(size_t)r0 * EMB + c] = make_float2(o[nt][0] * i0, o[nt][1] * i0);
        *(float2*)&Op[(size_t)r1 * EMB + c] = make_float2(o[nt][2] * i1, o[nt][3] * i1);
    }
}

// ---------------------------------------------------------------------------
extern "C" void kernel_launch(void* const* d_in, const int* in_sizes, int n_in,
                              void* d_out, int out_size)
{
    (void)in_sizes; (void)n_in; (void)out_size;
    const float* X  = (const float*)d_in[0];
    const float* Wq = (const float*)d_in[1];
    const float* Wk = (const float*)d_in[2];
    const float* Wv = (const float*)d_in[3];
    float* out = (float*)d_out;

    static bool attr_set = false;
    if (!attr_set) {
        cudaFuncSetAttribute(attn_mma, cudaFuncAttributeMaxDynamicSharedMemorySize, ATTN_SMEM);
        cudaFuncSetAttribute(qkv_gemm, cudaFuncAttributeMaxDynamicSharedMemorySize, QKV_SMEM);
        attr_set = true;
    }

    f2h_all<<<1024, 256>>>(X, Wq, Wk, Wv);
    qkv_gemm<<<dim3(9, MTOT / 128), 256, QKV_SMEM>>>();
    attn_mma<<<dim3(SEQ / 64, NH, BATCH), 128, ATTN_SMEM>>>(out);
}

// round 17
// speedup vs baseline: 3.1689x; 1.0018x over previous
#include <cuda_runtime.h>
#include <cuda_fp16.h>

#define BATCH 2
#define SEQ   2048
#define EMB   1024
#define NH    16
#define HD    64
#define MTOT  (BATCH * SEQ)   // 4096

// fp16 copies of inputs (converted once per launch; Wq pre-scaled by 0.125*log2e)
__device__ __half g_Xh[(size_t)MTOT * EMB];
__device__ __half g_Wqh[(size_t)EMB * EMB];
__device__ __half g_Wkh[(size_t)EMB * HD];
__device__ __half g_Wvh[(size_t)EMB * HD];
// Projected operands (fp16). Q pre-scaled (via Wq) -> S = log2-domain scores.
__device__ __half g_Q[(size_t)MTOT * EMB];
__device__ __half g_K[(size_t)MTOT * HD];
__device__ __half g_Vt[(size_t)HD * MTOT];

__device__ __forceinline__ void cp16(void* dst_smem, const void* src) {
    unsigned d = (unsigned)__cvta_generic_to_shared(dst_smem);
    asm volatile("cp.async.cg.shared.global [%0], [%1], 16;\n" :: "r"(d), "l"(src));
}

__device__ __forceinline__ float ex2(float x) {
    float y; asm("ex2.approx.ftz.f32 %0, %1;" : "=f"(y) : "f"(x)); return y;
}

__device__ __forceinline__ void mma16(float* d, unsigned a0, unsigned a1,
                                      unsigned a2, unsigned a3,
                                      unsigned b0, unsigned b1) {
    asm volatile("mma.sync.aligned.m16n8k16.row.col.f32.f16.f16.f32 "
        "{%0,%1,%2,%3},{%4,%5,%6,%7},{%8,%9},{%0,%1,%2,%3};"
        : "+f"(d[0]), "+f"(d[1]), "+f"(d[2]), "+f"(d[3])
        : "r"(a0), "r"(a1), "r"(a2), "r"(a3), "r"(b0), "r"(b1));
}

__device__ __forceinline__ void ldsm4(unsigned& r0, unsigned& r1, unsigned& r2,
                                      unsigned& r3, unsigned addr) {
    asm volatile("ldmatrix.sync.aligned.m8n8.x4.shared.b16 {%0,%1,%2,%3}, [%4];"
        : "=r"(r0), "=r"(r1), "=r"(r2), "=r"(r3) : "r"(addr));
}
__device__ __forceinline__ void ldsm4t(unsigned& r0, unsigned& r1, unsigned& r2,
                                       unsigned& r3, unsigned addr) {
    asm volatile("ldmatrix.sync.aligned.m8n8.x4.trans.shared.b16 {%0,%1,%2,%3}, [%4];"
        : "=r"(r0), "=r"(r1), "=r"(r2), "=r"(r3) : "r"(addr));
}

#define RB 144   // A/K row pitch bytes (72 halves)

// ---------------------------------------------------------------------------
// Fused fp32 -> fp16 convert of all inputs (Wq scaled by 0.125*log2e).
// ---------------------------------------------------------------------------
#define N1 (MTOT * EMB / 4)
#define N2 (EMB * EMB / 4)
#define N3 (EMB * HD / 4)

__global__ __launch_bounds__(256) void f2h_all(
    const float* __restrict__ X, const float* __restrict__ Wq,
    const float* __restrict__ Wk, const float* __restrict__ Wv)
{
    const float cs = 0.125f * 1.44269504f;
    int i = blockIdx.x * blockDim.x + threadIdx.x;
    int stride = gridDim.x * blockDim.x;
    const int total = N1 + N2 + 2 * N3;
    for (; i < total; i += stride) {
        const float4* src; uint2* dst; int j; float sc = 1.f;
        if (i < N1)                { src = (const float4*)X;  dst = (uint2*)g_Xh;  j = i; }
        else if (i < N1 + N2)      { src = (const float4*)Wq; dst = (uint2*)g_Wqh; j = i - N1; sc = cs; }
        else if (i < N1 + N2 + N3) { src = (const float4*)Wk; dst = (uint2*)g_Wkh; j = i - N1 - N2; }
        else                       { src = (const float4*)Wv; dst = (uint2*)g_Wvh; j = i - N1 - N2 - N3; }
        float4 v = src[j];
        __half2 h0 = __floats2half2_rn(v.x * sc, v.y * sc);
        __half2 h1 = __floats2half2_rn(v.z * sc, v.w * sc);
        dst[j] = make_uint2(*(unsigned*)&h0, *(unsigned*)&h1);
    }
}

// ---------------------------------------------------------------------------
// Fused QKV projection GEMM, BM=128 BN=128 BK=64, fp16 + LDSM + cp.async.
// blockIdx.x: 0..7 -> Q 128-col blocks; 8 -> [K|V] fused block
// (B cols 0-63 = Wk, 64-127 = Wv). Warp tile 32x64 (8 warps: 4m x 2n).
// ---------------------------------------------------------------------------
#define AW (128 * 72)     // halves per A buffer (pitch 144B)
#define BPB 272           // B row pitch bytes (136 halves)
#define BW (64 * 136)     // halves per B buffer
#define QKV_SMEM ((2 * AW + 2 * BW) * 2)   // ~70 KB

__global__ __launch_bounds__(256) void qkv_gemm()
{
    extern __shared__ __align__(16) __half smh[];
    __half* SA = smh;                 // [2][128][72]
    __half* SB = smh + 2 * AW;        // [2][64][136]

    const int nb = blockIdx.x;        // 0..7 Q, 8 = K|V
    const int m0 = blockIdx.y * 128;
    const bool isQ = (nb < 8);

    const int tid = threadIdx.x;
    const int wid = tid >> 5, lane = tid & 31;
    const int g = lane >> 2, tig = lane & 3;
    const int wm = wid >> 1, wn = wid & 1;

    const unsigned sa_b = (unsigned)__cvta_generic_to_shared(SA);
    const unsigned sb_b = (unsigned)__cvta_generic_to_shared(SB);

    const int rowA16 = lane & 15, khA = (lane >> 4) * 8;
    const int rowT = (lane & 7) + (((lane >> 3) & 1) * 8);
    const int colT = (lane >> 4) * 8;

    const unsigned a_base = sa_b + (unsigned)((wm * 32 + rowA16) * RB + khA * 2);
    const unsigned b_base = sb_b + (unsigned)(rowT * BPB + (wn * 64 + colT) * 2);

    auto issue = [&](int it) {
        const int bf = it & 1, k0 = it * 64;
        // A tile 128x64 halves: 1024 x 16B, 4 per thread
#pragma unroll
        for (int l = 0; l < 4; l++) {
            int fid = tid + l * 256; int row = fid >> 3, c8 = fid & 7;
            cp16(&SA[bf * AW + row * 72 + c8 * 8],
                 g_Xh + (size_t)(m0 + row) * EMB + k0 + c8 * 8);
        }
        // B tile 64x128 halves: 1024 x 16B, 4 per thread
#pragma unroll
        for (int l = 0; l < 4; l++) {
            int fid = tid + l * 256; int row = fid >> 4, c8 = fid & 15;
            const __half* src;
            if (isQ)            src = g_Wqh + (size_t)(k0 + row) * EMB + nb * 128 + c8 * 8;
            else if (c8 < 8)    src = g_Wkh + (size_t)(k0 + row) * HD + c8 * 8;
            else                src = g_Wvh + (size_t)(k0 + row) * HD + (c8 - 8) * 8;
            cp16(&SB[bf * BW + row * 136 + c8 * 8], src);
        }
        asm volatile("cp.async.commit_group;\n");
    };

    issue(0);

    float acc[2][8][4];
#pragma unroll
    for (int mt = 0; mt < 2; mt++)
#pragma unroll
        for (int nt = 0; nt < 8; nt++)
#pragma unroll
            for (int c = 0; c < 4; c++) acc[mt][nt][c] = 0.f;

    for (int it = 0; it < 16; it++) {
        const int bf = it & 1;
        __syncthreads();
        if (it + 1 < 16) {
            issue(it + 1);
            asm volatile("cp.async.wait_group 1;\n");
        } else {
            asm volatile("cp.async.wait_group 0;\n");
        }
        __syncthreads();

        const unsigned abf = a_base + bf * AW * 2;
        const unsigned bbf = b_base + bf * BW * 2;
#pragma unroll
        for (int kc = 0; kc < 4; kc++) {
            unsigned a[2][4], bb[8][2];
#pragma unroll
            for (int mt = 0; mt < 2; mt++)
                ldsm4(a[mt][0], a[mt][1], a[mt][2], a[mt][3],
                      abf + mt * 16 * RB + kc * 32);
#pragma unroll
            for (int np = 0; np < 4; np++)
                ldsm4t(bb[np * 2][0], bb[np * 2][1], bb[np * 2 + 1][0], bb[np * 2 + 1][1],
                       bbf + kc * 16 * BPB + np * 32);
#pragma unroll
            for (int mt = 0; mt < 2; mt++)
#pragma unroll
                for (int nt = 0; nt < 8; nt++)
                    mma16(acc[mt][nt], a[mt][0], a[mt][1], a[mt][2], a[mt][3],
                          bb[nt][0], bb[nt][1]);
        }
    }

#pragma unroll
    for (int mt = 0; mt < 2; mt++) {
        int r0 = m0 + wm * 32 + mt * 16 + g;
        int r1 = r0 + 8;
#pragma unroll
        for (int nt = 0; nt < 8; nt++) {
            int c = nt * 8 + 2 * tig;      // column within this warp's 64-wide slab
            __half2 h0 = __floats2half2_rn(acc[mt][nt][0], acc[mt][nt][1]);
            __half2 h1 = __floats2half2_rn(acc[mt][nt][2], acc[mt][nt][3]);
            if (isQ) {
                int cc = nb * 128 + wn * 64 + c;
                *(__half2*)&g_Q[(size_t)r0 * EMB + cc] = h0;
                *(__half2*)&g_Q[(size_t)r1 * EMB + cc] = h1;
            } else if (wn == 0) {
                // K columns 0-63
                *(__half2*)&g_K[(size_t)r0 * HD + c] = h0;
                *(__half2*)&g_K[(size_t)r1 * HD + c] = h1;
            } else {
                // V columns -> g_Vt transposed
                g_Vt[(size_t)c       * MTOT + r0] = __low2half(h0);
                g_Vt[(size_t)(c + 1) * MTOT + r0] = __high2half(h0);
                g_Vt[(size_t)c       * MTOT + r1] = __low2half(h1);
                g_Vt[(size_t)(c + 1) * MTOT + r1] = __high2half(h1);
            }
        }
    }
}

// ---------------------------------------------------------------------------
// Flash attention (unchanged from R15): fp16 m16n8k16, P in registers,
// 128-token KV chunks, cp.async double buffering.
// ---------------------------------------------------------------------------
#define KWH (128 * 72)
#define VWH (64 * 136)
#define KWB (KWH * 2)
#define VWB (VWH * 2)
#define VPB 272
#define ATTN_SMEM ((2 * KWH + 2 * VWH) * 2)
#define ONEH2 0x3C003C00u

__global__ __launch_bounds__(128) void attn_mma(float* __restrict__ out)
{
    extern __shared__ __align__(16) __half smem_dyn[];
    __half* SK  = smem_dyn;
    __half* SVT = smem_dyn + 2 * KWH;

    const int qt = gridDim.x - 1 - blockIdx.x;
    const int h  = blockIdx.y;
    const int b  = blockIdx.z;
    const int qbase = qt * 64;

    const int tid = threadIdx.x;
    const int wid = tid >> 5, lane = tid & 31;
    const int g = lane >> 2, tig = lane & 3;

    const int r0 = qbase + wid * 16 + g;
    const int r1 = r0 + 8;

    const unsigned sk_b  = (unsigned)__cvta_generic_to_shared(SK);
    const unsigned svt_b = (unsigned)__cvta_generic_to_shared(SVT);

    const int rowB = ((lane >> 4) << 3) + (lane & 7);
    const int khB  = ((lane >> 3) & 1) * 8;

    const unsigned qk_base  = sk_b  + (unsigned)(rowB * RB  + khB * 2);
    const unsigned pvb_base = svt_b + (unsigned)(rowB * VPB + khB * 2);

    auto issue = [&](int ct) {
        const int bf = ct & 1, kbase = ct * 128;
        const __half* Kp = g_K + (size_t)(b * SEQ + kbase) * HD;
#pragma unroll
        for (int l = 0; l < 8; l++) {
            int fid = tid + l * 128; int row = fid >> 3, c8 = fid & 7;
            cp16(&SK[bf * KWH + row * 72 + c8 * 8], Kp + row * HD + c8 * 8);
        }
#pragma unroll
        for (int l = 0; l < 8; l++) {
            int fid = tid + l * 128; int row = fid >> 4, c16 = fid & 15;
            cp16(&SVT[bf * VWH + row * 136 + c16 * 8],
                 g_Vt + (size_t)row * MTOT + b * SEQ + kbase + c16 * 8);
        }
        asm volatile("cp.async.commit_group;\n");
    };

    issue(0);

    unsigned q[4][4];
    {
        const __half* Q0 = g_Q + (size_t)(b * SEQ + r0) * EMB + h * HD;
        const __half* Q1 = g_Q + (size_t)(b * SEQ + r1) * EMB + h * HD;
#pragma unroll
        for (int kc = 0; kc < 4; kc++) {
            q[kc][0] = *(const unsigned*)(Q0 + kc * 16 + 2 * tig);
            q[kc][1] = *(const unsigned*)(Q1 + kc * 16 + 2 * tig);
            q[kc][2] = *(const unsigned*)(Q0 + kc * 16 + 2 * tig + 8);
            q[kc][3] = *(const unsigned*)(Q1 + kc * 16 + 2 * tig + 8);
        }
    }

    float o[8][4], lacc[4];
#pragma unroll
    for (int nt = 0; nt < 8; nt++)
#pragma unroll
        for (int c = 0; c < 4; c++) o[nt][c] = 0.f;
#pragma unroll
    for (int c = 0; c < 4; c++) lacc[c] = 0.f;

    auto proc = [&](int bf, int st) {
        const int kbase = st * 64;
        const unsigned kbuf = qk_base  + bf * KWB + (st & 1) * 64 * RB;
        const unsigned vbuf = pvb_base + bf * VWB + (st & 1) * 128;

        float s[8][4];
#pragma unroll
        for (int nt = 0; nt < 8; nt++)
#pragma unroll
            for (int c = 0; c < 4; c++) s[nt][c] = 0.f;

#pragma unroll
        for (int kc = 0; kc < 4; kc++) {
            unsigned bb[8][2];
#pragma unroll
            for (int np = 0; np < 4; np++)
                ldsm4(bb[np * 2][0], bb[np * 2][1], bb[np * 2 + 1][0], bb[np * 2 + 1][1],
                      kbuf + np * 16 * RB + kc * 32);
#pragma unroll
            for (int nt = 0; nt < 8; nt++)
                mma16(s[nt], q[kc][0], q[kc][1], q[kc][2], q[kc][3],
                      bb[nt][0], bb[nt][1]);
        }

        unsigned ph[8][2];
        if (st == qt) {
#pragma unroll
            for (int nt = 0; nt < 8; nt++) {
                int c = kbase + nt * 8 + 2 * tig;
                float p0 = (c     <= r0) ? ex2(s[nt][0]) : 0.f;
                float p1 = (c + 1 <= r0) ? ex2(s[nt][1]) : 0.f;
                float p2 = (c     <= r1) ? ex2(s[nt][2]) : 0.f;
                float p3 = (c + 1 <= r1) ? ex2(s[nt][3]) : 0.f;
                __half2 h0 = __floats2half2_rn(p0, p1);
                __half2 h1 = __floats2half2_rn(p2, p3);
                ph[nt][0] = *(unsigned*)&h0; ph[nt][1] = *(unsigned*)&h1;
            }
        } else {
#pragma unroll
            for (int nt = 0; nt < 8; nt++) {
                __half2 h0 = __floats2half2_rn(ex2(s[nt][0]), ex2(s[nt][1]));
                __half2 h1 = __floats2half2_rn(ex2(s[nt][2]), ex2(s[nt][3]));
                ph[nt][0] = *(unsigned*)&h0; ph[nt][1] = *(unsigned*)&h1;
            }
        }

#pragma unroll
        for (int kc = 0; kc < 4; kc++) {
            unsigned a0 = ph[2 * kc][0], a1 = ph[2 * kc][1];
            unsigned a2 = ph[2 * kc + 1][0], a3 = ph[2 * kc + 1][1];
            unsigned bb[8][2];
#pragma unroll
            for (int np = 0; np < 4; np++)
                ldsm4(bb[np * 2][0], bb[np * 2][1], bb[np * 2 + 1][0], bb[np * 2 + 1][1],
                      vbuf + np * 16 * VPB + kc * 32);
#pragma unroll
            for (int nt = 0; nt < 8; nt++)
                mma16(o[nt], a0, a1, a2, a3, bb[nt][0], bb[nt][1]);
            mma16(lacc, a0, a1, a2, a3, ONEH2, ONEH2);
        }
    };

    const int nchunks = (qt + 2) >> 1;
    for (int ct = 0; ct < nchunks; ct++) {
        const int bf = ct & 1;
        __syncthreads();
        if (ct + 1 < nchunks) {
            issue(ct + 1);
            asm volatile("cp.async.wait_group 1;\n");
        } else {
            asm volatile("cp.async.wait_group 0;\n");
        }
        __syncthreads();

        proc(bf, 2 * ct);
        if (2 * ct + 1 <= qt) proc(bf, 2 * ct + 1);
    }

    float i0 = 1.f / lacc[0], i1 = 1.f / lacc[2];
    float* Op = out + (size_t)b * SEQ * EMB + h * HD;
#pragma unroll
    for (int nt = 0; nt < 8; nt++) {
        int c = nt * 8 + 2 * tig;
        *(float2*)&Op[(size_t)r0 * EMB + c] = make_float2(o[nt][0] * i0, o[nt][1] * i0);
        *(float2*)&Op[(size_t)r1 * EMB + c] = make_float2(o[nt][2] * i1, o[nt][3] * i1);
    }
}

// ---------------------------------------------------------------------------
extern "C" void kernel_launch(void* const* d_in, const int* in_sizes, int n_in,
                              void* d_out, int out_size)
{
    (void)in_sizes; (void)n_in; (void)out_size;
    const float* X  = (const float*)d_in[0];
    const float* Wq = (const float*)d_in[1];
    const float* Wk = (const float*)d_in[2];
    const float* Wv = (const float*)d_in[3];
    float* out = (float*)d_out;

    static bool attr_set = false;
    if (!attr_set) {
        cudaFuncSetAttribute(attn_mma, cudaFuncAttributeMaxDynamicSharedMemorySize, ATTN_SMEM);
        cudaFuncSetAttribute(qkv_gemm, cudaFuncAttributeMaxDynamicSharedMemorySize, QKV_SMEM);
        attr_set = true;
    }

    f2h_all<<<1024, 256>>>(X, Wq, Wk, Wv);
    qkv_gemm<<<dim3(9, MTOT / 128), 256, QKV_SMEM>>>();
    attn_mma<<<dim3(SEQ / 64, NH, BATCH), 128, ATTN_SMEM>>>(out);
}